// round 8
// baseline (speedup 1.0000x reference)
#include <cuda_runtime.h>
#include <cstdint>

// ---------------------------------------------------------------------------
// img_attn: B=32, Nv=1556, Ni=256, N=1812 tokens, D=512, IMG_D=2048
//
//  G1 gemm:  img_f @ fc_w^T + fc_b            -> g_xi
//  G2 gemm:  split(verts,g_xi) @ q_w^T + q_b  -> g_q   (+row stats partials)
//  G3 gemm:  split(verts,g_xi) @ k_w^T + k_b  -> g_k   (+row stats partials)
//  K4 rowstat_lite: combine partials -> qs, ks, logits a
//  K5 softmax; K6 gsum+reduce; K7 ymul
//  G4 gemm:  y @ proj_w^T + proj_b + qs*q  -> g_o1
//  G5 gemm:  g_o1 @ final_w^T + final_b + verts -> out
//
// GEMM: 128x256 CTA tile, 64x64 warp tile (8 warps), tf32 m16n8k8 fed raw
// fp32 bits, 3-stage cp.async pipeline (wait_group 1), fragment double
// buffering, 1 CTA/SM (255 reg budget). Epilogue fuses bias/E/stats.
// ---------------------------------------------------------------------------

#define BATCH 32
#define NVERT 1556
#define NIMG  256
#define NTOK  1812
#define DIM   512
#define IMGDIM 2048
#define M_ALL (BATCH * NTOK)    // 57984
#define M_VRT (BATCH * NVERT)   // 49792
#define M_IMG (BATCH * NIMG)    // 8192
#define ATT_SCALE 0.08838834764831845f
#define NSPLIT 16

__device__ __align__(256) float g_xi[(size_t)M_IMG * DIM];
__device__ __align__(256) float g_q [(size_t)M_ALL * DIM];
__device__ __align__(256) float g_k [(size_t)M_ALL * DIM];
__device__ __align__(256) float g_y [(size_t)M_VRT * DIM];
__device__ __align__(256) float g_o1[(size_t)M_VRT * DIM];
__device__ __align__(256) float g_a [M_ALL];
__device__ __align__(256) float g_qs[M_ALL];
__device__ __align__(256) float g_ks[M_ALL];
__device__ __align__(256) float g_g [BATCH * DIM];
__device__ __align__(256) float g_gp[NSPLIT * BATCH * DIM];
__device__ __align__(256) float g_pq1[2 * M_ALL];   // ssq(q) partials per N-half
__device__ __align__(256) float g_pq2[2 * M_ALL];   // q.wg partials
__device__ __align__(256) float g_pk1[2 * M_ALL];   // ssq(k) partials

struct RMap { int div, stride, off; };
__device__ __forceinline__ int rmap_apply(const RMap m, int r) {
    int q = r / m.div;
    return q * m.stride + (r - q * m.div) + m.off;
}

__device__ __forceinline__ void mma_tf32(float* d, const uint32_t* a, const uint32_t* b) {
    asm volatile(
        "mma.sync.aligned.m16n8k8.row.col.f32.tf32.tf32.f32 "
        "{%0,%1,%2,%3},{%4,%5,%6,%7},{%8,%9},{%0,%1,%2,%3};"
        : "+f"(d[0]), "+f"(d[1]), "+f"(d[2]), "+f"(d[3])
        : "r"(a[0]), "r"(a[1]), "r"(a[2]), "r"(a[3]), "r"(b[0]), "r"(b[1]));
}

#define BM 128
#define BN 256
#define SSTR 36
#define STAGE_FLOATS ((BM + BN) * SSTR)          // 13824
#define GEMM_SMEM (3 * STAGE_FLOATS * (int)sizeof(float))   // 165888 B

// MODE: 0 = plain, 1 = q stats (ssq + dot wg), 2 = k stats (ssq)
template<int MODE>
__global__ __launch_bounds__(256, 1)
void gemm_tc(const float* __restrict__ A0, const float* __restrict__ A1,
             const float* __restrict__ Bw, const float* __restrict__ bias,
             const float* __restrict__ E, const float* __restrict__ escale,
             const float* __restrict__ wg,
             float* __restrict__ C, float* __restrict__ P1, float* __restrict__ P2,
             int K, int Mtot, RMap cmap, RMap emap)
{
    extern __shared__ float sm[];
    const int tid  = threadIdx.x;
    const int lane = tid & 31;
    const int warp = tid >> 5;
    const int wm   = warp >> 2;           // 0..1  rows 64 each
    const int wn   = warp & 3;            // 0..3  cols 64 each
    const long rowA0 = (long)blockIdx.y * BM;
    const long rowB0 = (long)blockIdx.x * BN;

    // A-row source pointers (two-source token split when A1 != null)
    const float* arow[4];
#pragma unroll
    for (int j = 0; j < 4; j++) {
        const int r = (tid + j * 256) >> 3;
        const long rr = rowA0 + r;
        if (A1) {
            const int b = (int)(rr / NTOK);
            const int t = (int)(rr - (long)b * NTOK);
            arow[j] = (t < NVERT) ? A0 + ((size_t)b * NVERT + t) * DIM
                                  : A1 + ((size_t)b * NIMG + (t - NVERT)) * DIM;
        } else {
            arow[j] = A0 + rr * (long)K;
        }
    }

    float acc[4][8][4];
#pragma unroll
    for (int mt = 0; mt < 4; mt++)
#pragma unroll
        for (int nt = 0; nt < 8; nt++)
#pragma unroll
            for (int i = 0; i < 4; i++) acc[mt][nt][i] = 0.f;

    auto load_tiles = [&](int t) {
        const int s = t % 3;
        const int k0 = t * 32;
        float* As = sm + s * STAGE_FLOATS;
        float* Bs = As + BM * SSTR;
#pragma unroll
        for (int j = 0; j < 4; j++) {
            const int idx = tid + j * 256;
            const int r = idx >> 3;
            const int c = (idx & 7) << 2;
            uint32_t sp = (uint32_t)__cvta_generic_to_shared(As + r * SSTR + c);
            asm volatile("cp.async.cg.shared.global [%0], [%1], 16;"
                         :: "r"(sp), "l"(arow[j] + k0 + c));
        }
#pragma unroll
        for (int j = 0; j < 8; j++) {
            const int idx = tid + j * 256;
            const int r = idx >> 3;
            const int c = (idx & 7) << 2;
            uint32_t sp = (uint32_t)__cvta_generic_to_shared(Bs + r * SSTR + c);
            asm volatile("cp.async.cg.shared.global [%0], [%1], 16;"
                         :: "r"(sp), "l"(Bw + (rowB0 + r) * (long)K + k0 + c));
        }
        asm volatile("cp.async.commit_group;" ::: "memory");
    };

    const int T = K / 32;
    load_tiles(0);
    load_tiles(1);

    uint32_t af[2][4][4], bf[2][8][2];

    for (int t = 0; t < T; t++) {
        if (t < T - 1) asm volatile("cp.async.wait_group 1;" ::: "memory");
        else           asm volatile("cp.async.wait_group 0;" ::: "memory");
        __syncthreads();
        if (t + 2 < T) load_tiles(t + 2);

        const uint32_t* Ab = (const uint32_t*)(sm + (t % 3) * STAGE_FLOATS);
        const uint32_t* Bb = Ab + BM * SSTR;

        // fragment double-buffered k-steps
        {
            const int kc = lane & 3;
#pragma unroll
            for (int mt = 0; mt < 4; mt++) {
                const int r = wm * 64 + mt * 16 + (lane >> 2);
                af[0][mt][0] = Ab[r * SSTR + kc];
                af[0][mt][1] = Ab[(r + 8) * SSTR + kc];
                af[0][mt][2] = Ab[r * SSTR + kc + 4];
                af[0][mt][3] = Ab[(r + 8) * SSTR + kc + 4];
            }
#pragma unroll
            for (int nt = 0; nt < 8; nt++) {
                const int n = wn * 64 + nt * 8 + (lane >> 2);
                bf[0][nt][0] = Bb[n * SSTR + kc];
                bf[0][nt][1] = Bb[n * SSTR + kc + 4];
            }
        }
#pragma unroll
        for (int ks = 0; ks < 4; ks++) {
            const int cur = ks & 1;
            if (ks < 3) {
                const int nxt = cur ^ 1;
                const int kc = (ks + 1) * 8 + (lane & 3);
#pragma unroll
                for (int mt = 0; mt < 4; mt++) {
                    const int r = wm * 64 + mt * 16 + (lane >> 2);
                    af[nxt][mt][0] = Ab[r * SSTR + kc];
                    af[nxt][mt][1] = Ab[(r + 8) * SSTR + kc];
                    af[nxt][mt][2] = Ab[r * SSTR + kc + 4];
                    af[nxt][mt][3] = Ab[(r + 8) * SSTR + kc + 4];
                }
#pragma unroll
                for (int nt = 0; nt < 8; nt++) {
                    const int n = wn * 64 + nt * 8 + (lane >> 2);
                    bf[nxt][nt][0] = Bb[n * SSTR + kc];
                    bf[nxt][nt][1] = Bb[n * SSTR + kc + 4];
                }
            }
#pragma unroll
            for (int mt = 0; mt < 4; mt++)
#pragma unroll
                for (int nt = 0; nt < 8; nt++)
                    mma_tf32(acc[mt][nt], af[cur][mt], bf[cur][nt]);
        }
    }

    // ---- epilogue: bias (+ escale*E), optional row-stat partials ----
    float st_sq0[4], st_sq1[4], st_dw0[4], st_dw1[4];

#pragma unroll
    for (int mt = 0; mt < 4; mt++) {
        const int gr0 = (int)rowA0 + wm * 64 + mt * 16 + (lane >> 2);
        const int gr1 = gr0 + 8;
        const int cr0 = rmap_apply(cmap, gr0);
        const int cr1 = rmap_apply(cmap, gr1);
        int er0 = 0, er1 = 0;
        float es0 = 1.f, es1 = 1.f;
        if (E) {
            er0 = rmap_apply(emap, gr0); er1 = rmap_apply(emap, gr1);
            if (escale) { es0 = escale[er0]; es1 = escale[er1]; }
        }
        float ssq0 = 0.f, ssq1 = 0.f, sdw0 = 0.f, sdw1 = 0.f;
#pragma unroll
        for (int nt = 0; nt < 8; nt++) {
            const int gc = (int)rowB0 + wn * 64 + nt * 8 + ((lane & 3) << 1);
            const float2 bb = *(const float2*)(bias + gc);
            float2 v0 = make_float2(acc[mt][nt][0] + bb.x, acc[mt][nt][1] + bb.y);
            float2 v1 = make_float2(acc[mt][nt][2] + bb.x, acc[mt][nt][3] + bb.y);
            if (E) {
                const float2 e0 = *(const float2*)(E + (size_t)er0 * DIM + gc);
                const float2 e1 = *(const float2*)(E + (size_t)er1 * DIM + gc);
                v0.x += es0 * e0.x; v0.y += es0 * e0.y;
                v1.x += es1 * e1.x; v1.y += es1 * e1.y;
            }
            *(float2*)(C + (size_t)cr0 * DIM + gc) = v0;
            *(float2*)(C + (size_t)cr1 * DIM + gc) = v1;
            if (MODE) {
                ssq0 += v0.x * v0.x + v0.y * v0.y;
                ssq1 += v1.x * v1.x + v1.y * v1.y;
                if (MODE == 1) {
                    const float2 w2 = *(const float2*)(wg + gc);
                    sdw0 += v0.x * w2.x + v0.y * w2.y;
                    sdw1 += v1.x * w2.x + v1.y * w2.y;
                }
            }
        }
        st_sq0[mt] = ssq0; st_sq1[mt] = ssq1;
        st_dw0[mt] = sdw0; st_dw1[mt] = sdw1;
    }

    if (MODE) {
        __syncthreads();                      // smem stages no longer needed
        float* s1 = sm;                       // [128][4]
        float* s2 = sm + 128 * 4;             // [128][4]
#pragma unroll
        for (int mt = 0; mt < 4; mt++) {
            float a0 = st_sq0[mt], a1 = st_sq1[mt];
            float b0 = st_dw0[mt], b1 = st_dw1[mt];
#pragma unroll
            for (int o = 1; o <= 2; o <<= 1) {
                a0 += __shfl_xor_sync(0xffffffffu, a0, o);
                a1 += __shfl_xor_sync(0xffffffffu, a1, o);
                if (MODE == 1) {
                    b0 += __shfl_xor_sync(0xffffffffu, b0, o);
                    b1 += __shfl_xor_sync(0xffffffffu, b1, o);
                }
            }
            if ((lane & 3) == 0) {
                const int r0 = wm * 64 + mt * 16 + (lane >> 2);
                const int r1 = r0 + 8;
                s1[r0 * 4 + wn] = a0; s1[r1 * 4 + wn] = a1;
                if (MODE == 1) { s2[r0 * 4 + wn] = b0; s2[r1 * 4 + wn] = b1; }
            }
        }
        __syncthreads();
        if (tid < 128) {
            const size_t dst = (size_t)blockIdx.x * Mtot + rowA0 + tid;
            P1[dst] = s1[tid * 4] + s1[tid * 4 + 1] + s1[tid * 4 + 2] + s1[tid * 4 + 3];
            if (MODE == 1)
                P2[dst] = s2[tid * 4] + s2[tid * 4 + 1] + s2[tid * 4 + 2] + s2[tid * 4 + 3];
        }
    }
}

// ---------------------------------------------------------------------------
// Small kernels
// ---------------------------------------------------------------------------

__global__ __launch_bounds__(256)
void rowstat_lite_kernel() {
    const int r = blockIdx.x * 256 + threadIdx.x;
    if (r >= M_ALL) return;
    const float ssq = g_pq1[r] + g_pq1[M_ALL + r];
    const float sdw = g_pq2[r] + g_pq2[M_ALL + r];
    const float ssk = g_pk1[r] + g_pk1[M_ALL + r];
    const float qs = 1.0f / fmaxf(sqrtf(ssq), 1e-12f);
    g_qs[r] = qs;
    g_ks[r] = 1.0f / fmaxf(sqrtf(ssk), 1e-12f);
    g_a[r]  = sdw * qs * ATT_SCALE;
}

__global__ __launch_bounds__(256)
void softmax_kernel() {
    const int b = blockIdx.x;
    const int tid = threadIdx.x;
    __shared__ float sh[NTOK];
    __shared__ float red[8];
    __shared__ float stat[2];
    float m = -1e30f;
    for (int i = tid; i < NTOK; i += 256) {
        const float v = g_a[b * NTOK + i]; sh[i] = v; m = fmaxf(m, v);
    }
#pragma unroll
    for (int o = 16; o > 0; o >>= 1) m = fmaxf(m, __shfl_down_sync(0xffffffffu, m, o));
    if ((tid & 31) == 0) red[tid >> 5] = m;
    __syncthreads();
    if (tid == 0) {
        float mm = red[0];
        for (int i = 1; i < 8; i++) mm = fmaxf(mm, red[i]);
        stat[0] = mm;
    }
    __syncthreads();
    const float M = stat[0];
    float s = 0.f;
    for (int i = tid; i < NTOK; i += 256) {
        const float e = expf(sh[i] - M); sh[i] = e; s += e;
    }
#pragma unroll
    for (int o = 16; o > 0; o >>= 1) s += __shfl_down_sync(0xffffffffu, s, o);
    __syncthreads();
    if ((tid & 31) == 0) red[tid >> 5] = s;
    __syncthreads();
    if (tid == 0) {
        float t = 0.f;
        for (int i = 0; i < 8; i++) t += red[i];
        stat[1] = 1.0f / t;
    }
    __syncthreads();
    const float inv = stat[1];
    for (int i = tid; i < NTOK; i += 256) g_a[b * NTOK + i] = sh[i] * inv;
}

__global__ __launch_bounds__(256)
void gsum_kernel() {
    const int b = blockIdx.x;
    const int d = threadIdx.x * 2;
    float ax = 0.f, ay = 0.f;
    for (int n = blockIdx.y; n < NTOK; n += NSPLIT) {
        const int row = b * NTOK + n;
        const float w = g_a[row] * g_qs[row];
        const float2 qv = *(const float2*)(g_q + (size_t)row * DIM + d);
        ax += w * qv.x; ay += w * qv.y;
    }
    g_gp[(size_t)blockIdx.y * BATCH * DIM + b * DIM + d]     = ax;
    g_gp[(size_t)blockIdx.y * BATCH * DIM + b * DIM + d + 1] = ay;
}

__global__ __launch_bounds__(256)
void greduce_kernel() {
    const int i = blockIdx.x * 256 + threadIdx.x;
    float s = 0.f;
#pragma unroll
    for (int p = 0; p < NSPLIT; p++) s += g_gp[(size_t)p * BATCH * DIM + i];
    g_g[i] = s;
}

__global__ __launch_bounds__(256)
void ymul_kernel() {
    const int idx = blockIdx.x * 256 + threadIdx.x;
    const int m = idx >> 7, j = idx & 127;
    const int b = m / NVERT, t = m - b * NVERT;
    const int row = b * NTOK + t;
    const float ks = g_ks[row];
    const float4 kv = ((const float4*)g_k)[(size_t)row * 128 + j];
    const float4 gv = ((const float4*)g_g)[b * 128 + j];
    ((float4*)g_y)[idx] = make_float4(kv.x * gv.x * ks, kv.y * gv.y * ks,
                                      kv.z * gv.z * ks, kv.w * gv.w * ks);
}

// ---------------------------------------------------------------------------

extern "C" void kernel_launch(void* const* d_in, const int* in_sizes, int n_in,
                              void* d_out, int out_size) {
    const float* verts   = (const float*)d_in[0];
    const float* img_f   = (const float*)d_in[1];
    const float* fc_w    = (const float*)d_in[2];
    const float* fc_b    = (const float*)d_in[3];
    const float* q_w     = (const float*)d_in[4];
    const float* q_b     = (const float*)d_in[5];
    const float* k_w     = (const float*)d_in[6];
    const float* k_b     = (const float*)d_in[7];
    const float* w_g     = (const float*)d_in[8];
    const float* proj_w  = (const float*)d_in[9];
    const float* proj_b  = (const float*)d_in[10];
    const float* final_w = (const float*)d_in[11];
    const float* final_b = (const float*)d_in[12];
    float* out = (float*)d_out;

    float *pxi, *pq, *pk, *py, *po1, *pqs, *ppq1, *ppq2, *ppk1;
    cudaGetSymbolAddress((void**)&pxi,  g_xi);
    cudaGetSymbolAddress((void**)&pq,   g_q);
    cudaGetSymbolAddress((void**)&pk,   g_k);
    cudaGetSymbolAddress((void**)&py,   g_y);
    cudaGetSymbolAddress((void**)&po1,  g_o1);
    cudaGetSymbolAddress((void**)&pqs,  g_qs);
    cudaGetSymbolAddress((void**)&ppq1, g_pq1);
    cudaGetSymbolAddress((void**)&ppq2, g_pq2);
    cudaGetSymbolAddress((void**)&ppk1, g_pk1);

    cudaFuncSetAttribute(gemm_tc<0>, cudaFuncAttributeMaxDynamicSharedMemorySize, GEMM_SMEM);
    cudaFuncSetAttribute(gemm_tc<1>, cudaFuncAttributeMaxDynamicSharedMemorySize, GEMM_SMEM);
    cudaFuncSetAttribute(gemm_tc<2>, cudaFuncAttributeMaxDynamicSharedMemorySize, GEMM_SMEM);

    const RMap direct    = {1 << 30, 0, 0};
    const RMap vert_emap = {NVERT, NTOK, 0};

    // G1: img projection
    gemm_tc<0><<<dim3(DIM / BN, M_IMG / BM), 256, GEMM_SMEM>>>(
        img_f, nullptr, fc_w, fc_b, nullptr, nullptr, nullptr,
        pxi, nullptr, nullptr, IMGDIM, 0, direct, direct);
    // G2: q (+stats)
    gemm_tc<1><<<dim3(DIM / BN, M_ALL / BM), 256, GEMM_SMEM>>>(
        verts, pxi, q_w, q_b, nullptr, nullptr, w_g,
        pq, ppq1, ppq2, DIM, M_ALL, direct, direct);
    // G3: k (+stats)
    gemm_tc<2><<<dim3(DIM / BN, M_ALL / BM), 256, GEMM_SMEM>>>(
        verts, pxi, k_w, k_b, nullptr, nullptr, nullptr,
        pk, ppk1, nullptr, DIM, M_ALL, direct, direct);
    rowstat_lite_kernel<<<(M_ALL + 255) / 256, 256>>>();
    softmax_kernel<<<BATCH, 256>>>();
    gsum_kernel<<<dim3(BATCH, NSPLIT), 256>>>();
    greduce_kernel<<<(BATCH * DIM) / 256, 256>>>();
    ymul_kernel<<<(M_VRT * 128) / 256, 256>>>();
    // G4: proj + qs*q residual
    gemm_tc<0><<<dim3(DIM / BN, M_VRT / BM), 256, GEMM_SMEM>>>(
        py, nullptr, proj_w, proj_b, pq, pqs, nullptr,
        po1, nullptr, nullptr, DIM, 0, direct, vert_emap);
    // G5: final + verts residual
    gemm_tc<0><<<dim3(DIM / BN, M_VRT / BM), 256, GEMM_SMEM>>>(
        po1, nullptr, final_w, final_b, verts, nullptr, nullptr,
        out, nullptr, nullptr, DIM, 0, direct, direct);
}

// round 9
// speedup vs baseline: 1.5482x; 1.5482x over previous
#include <cuda_runtime.h>
#include <cstdint>

// ---------------------------------------------------------------------------
// img_attn: B=32, Nv=1556, Ni=256, N=1812 tokens, D=512, IMG_D=2048
//
//  G1 gemm:  img_f @ fc_w^T + fc_b            -> g_xi
//  G2 gemm:  split(verts,g_xi) @ q_w^T + q_b  -> g_q   (+row stat partials)
//  G3 gemm:  split(verts,g_xi) @ k_w^T + k_b  -> g_k   (+row stat partials)
//  K4 rowstat_lite: combine partials -> qs, ks, logits a
//  K5 softmax; K6 gsum+reduce; K7 ymul
//  G4 gemm:  y @ proj_w^T + proj_b + qs*q  -> g_o1
//  G5 gemm:  g_o1 @ final_w^T + final_b + verts -> out
//
// GEMM: 128x128 CTA tile, 64x32 warp tile, tf32 m16n8k8 fed raw fp32 bits,
// 3-stage cp.async pipeline (wait_group 1), 256 threads, 2 CTAs/SM.
// ---------------------------------------------------------------------------

#define BATCH 32
#define NVERT 1556
#define NIMG  256
#define NTOK  1812
#define DIM   512
#define IMGDIM 2048
#define M_ALL (BATCH * NTOK)    // 57984
#define M_VRT (BATCH * NVERT)   // 49792
#define M_IMG (BATCH * NIMG)    // 8192
#define ATT_SCALE 0.08838834764831845f
#define NSPLIT 16
#define NCT 4                   // DIM / BN column tiles -> stat partials per row

__device__ __align__(256) float g_xi[(size_t)M_IMG * DIM];
__device__ __align__(256) float g_q [(size_t)M_ALL * DIM];
__device__ __align__(256) float g_k [(size_t)M_ALL * DIM];
__device__ __align__(256) float g_y [(size_t)M_VRT * DIM];
__device__ __align__(256) float g_o1[(size_t)M_VRT * DIM];
__device__ __align__(256) float g_a [M_ALL];
__device__ __align__(256) float g_qs[M_ALL];
__device__ __align__(256) float g_ks[M_ALL];
__device__ __align__(256) float g_g [BATCH * DIM];
__device__ __align__(256) float g_gp[NSPLIT * BATCH * DIM];
__device__ __align__(256) float g_pq1[NCT * M_ALL];   // ssq(q) partials
__device__ __align__(256) float g_pq2[NCT * M_ALL];   // q.wg partials
__device__ __align__(256) float g_pk1[NCT * M_ALL];   // ssq(k) partials

struct RMap { int div, stride, off; };
__device__ __forceinline__ int rmap_apply(const RMap m, int r) {
    int q = r / m.div;
    return q * m.stride + (r - q * m.div) + m.off;
}

__device__ __forceinline__ void mma_tf32(float* d, const uint32_t* a, const uint32_t* b) {
    asm volatile(
        "mma.sync.aligned.m16n8k8.row.col.f32.tf32.tf32.f32 "
        "{%0,%1,%2,%3},{%4,%5,%6,%7},{%8,%9},{%0,%1,%2,%3};"
        : "+f"(d[0]), "+f"(d[1]), "+f"(d[2]), "+f"(d[3])
        : "r"(a[0]), "r"(a[1]), "r"(a[2]), "r"(a[3]), "r"(b[0]), "r"(b[1]));
}

#define BM 128
#define BN 128
#define SSTR 36
#define STAGE_FLOATS ((BM + BN) * SSTR)                      // 9216
#define GEMM_SMEM (3 * STAGE_FLOATS * (int)sizeof(float))    // 110592 B

// MODE: 0 = plain, 1 = q stats (ssq + dot wg), 2 = k stats (ssq)
template<int MODE>
__global__ __launch_bounds__(256, 2)
void gemm_tc(const float* __restrict__ A0, const float* __restrict__ A1,
             const float* __restrict__ Bw, const float* __restrict__ bias,
             const float* __restrict__ E, const float* __restrict__ escale,
             const float* __restrict__ wg,
             float* __restrict__ C, float* __restrict__ P1, float* __restrict__ P2,
             int K, int Mtot, RMap cmap, RMap emap)
{
    extern __shared__ float sm[];
    const int tid  = threadIdx.x;
    const int lane = tid & 31;
    const int warp = tid >> 5;
    const int wm   = warp >> 2;           // 0..1 -> 64 rows
    const int wn   = warp & 3;            // 0..3 -> 32 cols
    const long rowA0 = (long)blockIdx.y * BM;
    const long rowB0 = (long)blockIdx.x * BN;

    // A-row source pointers (two-source token split when A1 != null)
    const float* arow[4];
#pragma unroll
    for (int j = 0; j < 4; j++) {
        const int r = (tid + j * 256) >> 3;
        const long rr = rowA0 + r;
        if (A1) {
            const int b = (int)(rr / NTOK);
            const int t = (int)(rr - (long)b * NTOK);
            arow[j] = (t < NVERT) ? A0 + ((size_t)b * NVERT + t) * DIM
                                  : A1 + ((size_t)b * NIMG + (t - NVERT)) * DIM;
        } else {
            arow[j] = A0 + rr * (long)K;
        }
    }

    float acc[4][4][4];
#pragma unroll
    for (int mt = 0; mt < 4; mt++)
#pragma unroll
        for (int nt = 0; nt < 4; nt++)
#pragma unroll
            for (int i = 0; i < 4; i++) acc[mt][nt][i] = 0.f;

    auto load_tiles = [&](int t) {
        float* As = sm + (t % 3) * STAGE_FLOATS;
        float* Bs = As + BM * SSTR;
        const int k0 = t * 32;
#pragma unroll
        for (int j = 0; j < 4; j++) {
            const int idx = tid + j * 256;
            const int r = idx >> 3;
            const int c = (idx & 7) << 2;
            {
                uint32_t sp = (uint32_t)__cvta_generic_to_shared(As + r * SSTR + c);
                asm volatile("cp.async.cg.shared.global [%0], [%1], 16;"
                             :: "r"(sp), "l"(arow[j] + k0 + c));
            }
            {
                uint32_t sp = (uint32_t)__cvta_generic_to_shared(Bs + r * SSTR + c);
                asm volatile("cp.async.cg.shared.global [%0], [%1], 16;"
                             :: "r"(sp), "l"(Bw + (rowB0 + r) * (long)K + k0 + c));
            }
        }
        asm volatile("cp.async.commit_group;" ::: "memory");
    };

    const int T = K / 32;
    load_tiles(0);
    load_tiles(1);

    for (int t = 0; t < T; t++) {
        if (t < T - 1) asm volatile("cp.async.wait_group 1;" ::: "memory");
        else           asm volatile("cp.async.wait_group 0;" ::: "memory");
        __syncthreads();
        if (t + 2 < T) load_tiles(t + 2);

        const uint32_t* Ab = (const uint32_t*)(sm + (t % 3) * STAGE_FLOATS);
        const uint32_t* Bb = Ab + BM * SSTR;
#pragma unroll
        for (int ks = 0; ks < 4; ks++) {
            const int kc = ks * 8 + (lane & 3);
            uint32_t af[4][4], bf[4][2];
#pragma unroll
            for (int mt = 0; mt < 4; mt++) {
                const int r = wm * 64 + mt * 16 + (lane >> 2);
                af[mt][0] = Ab[r * SSTR + kc];          // raw fp32 bits: HW
                af[mt][1] = Ab[(r + 8) * SSTR + kc];    // truncates to tf32
                af[mt][2] = Ab[r * SSTR + kc + 4];
                af[mt][3] = Ab[(r + 8) * SSTR + kc + 4];
            }
#pragma unroll
            for (int nt = 0; nt < 4; nt++) {
                const int n = wn * 32 + nt * 8 + (lane >> 2);
                bf[nt][0] = Bb[n * SSTR + kc];
                bf[nt][1] = Bb[n * SSTR + kc + 4];
            }
#pragma unroll
            for (int mt = 0; mt < 4; mt++)
#pragma unroll
                for (int nt = 0; nt < 4; nt++)
                    mma_tf32(acc[mt][nt], af[mt], bf[nt]);
        }
    }

    // ---- epilogue: bias (+ escale*E), optional row-stat partials ----
    float st_sq0[4], st_sq1[4], st_dw0[4], st_dw1[4];

#pragma unroll
    for (int mt = 0; mt < 4; mt++) {
        const int gr0 = (int)rowA0 + wm * 64 + mt * 16 + (lane >> 2);
        const int gr1 = gr0 + 8;
        const int cr0 = rmap_apply(cmap, gr0);
        const int cr1 = rmap_apply(cmap, gr1);
        int er0 = 0, er1 = 0;
        float es0 = 1.f, es1 = 1.f;
        if (E) {
            er0 = rmap_apply(emap, gr0); er1 = rmap_apply(emap, gr1);
            if (escale) { es0 = escale[er0]; es1 = escale[er1]; }
        }
        float ssq0 = 0.f, ssq1 = 0.f, sdw0 = 0.f, sdw1 = 0.f;
#pragma unroll
        for (int nt = 0; nt < 4; nt++) {
            const int gc = (int)rowB0 + wn * 32 + nt * 8 + ((lane & 3) << 1);
            const float2 bb = *(const float2*)(bias + gc);
            float2 v0 = make_float2(acc[mt][nt][0] + bb.x, acc[mt][nt][1] + bb.y);
            float2 v1 = make_float2(acc[mt][nt][2] + bb.x, acc[mt][nt][3] + bb.y);
            if (E) {
                const float2 e0 = *(const float2*)(E + (size_t)er0 * DIM + gc);
                const float2 e1 = *(const float2*)(E + (size_t)er1 * DIM + gc);
                v0.x += es0 * e0.x; v0.y += es0 * e0.y;
                v1.x += es1 * e1.x; v1.y += es1 * e1.y;
            }
            *(float2*)(C + (size_t)cr0 * DIM + gc) = v0;
            *(float2*)(C + (size_t)cr1 * DIM + gc) = v1;
            if (MODE) {
                ssq0 += v0.x * v0.x + v0.y * v0.y;
                ssq1 += v1.x * v1.x + v1.y * v1.y;
                if (MODE == 1) {
                    const float2 w2 = *(const float2*)(wg + gc);
                    sdw0 += v0.x * w2.x + v0.y * w2.y;
                    sdw1 += v1.x * w2.x + v1.y * w2.y;
                }
            }
        }
        st_sq0[mt] = ssq0; st_sq1[mt] = ssq1;
        st_dw0[mt] = sdw0; st_dw1[mt] = sdw1;
    }

    if (MODE) {
        __syncthreads();                      // smem stages no longer needed
        float* s1 = sm;                       // [128][4]
        float* s2 = sm + 128 * 4;             // [128][4]
#pragma unroll
        for (int mt = 0; mt < 4; mt++) {
            float a0 = st_sq0[mt], a1 = st_sq1[mt];
            float b0 = st_dw0[mt], b1 = st_dw1[mt];
#pragma unroll
            for (int o = 1; o <= 2; o <<= 1) {
                a0 += __shfl_xor_sync(0xffffffffu, a0, o);
                a1 += __shfl_xor_sync(0xffffffffu, a1, o);
                if (MODE == 1) {
                    b0 += __shfl_xor_sync(0xffffffffu, b0, o);
                    b1 += __shfl_xor_sync(0xffffffffu, b1, o);
                }
            }
            if ((lane & 3) == 0) {
                const int r0 = wm * 64 + mt * 16 + (lane >> 2);
                const int r1 = r0 + 8;
                s1[r0 * 4 + wn] = a0; s1[r1 * 4 + wn] = a1;
                if (MODE == 1) { s2[r0 * 4 + wn] = b0; s2[r1 * 4 + wn] = b1; }
            }
        }
        __syncthreads();
        if (tid < 128) {
            const size_t dst = (size_t)blockIdx.x * Mtot + rowA0 + tid;
            P1[dst] = s1[tid * 4] + s1[tid * 4 + 1] + s1[tid * 4 + 2] + s1[tid * 4 + 3];
            if (MODE == 1)
                P2[dst] = s2[tid * 4] + s2[tid * 4 + 1] + s2[tid * 4 + 2] + s2[tid * 4 + 3];
        }
    }
}

// ---------------------------------------------------------------------------
// Small kernels
// ---------------------------------------------------------------------------

__global__ __launch_bounds__(256)
void rowstat_lite_kernel() {
    const int r = blockIdx.x * 256 + threadIdx.x;
    if (r >= M_ALL) return;
    float ssq = 0.f, sdw = 0.f, ssk = 0.f;
#pragma unroll
    for (int p = 0; p < NCT; p++) {
        ssq += g_pq1[p * M_ALL + r];
        sdw += g_pq2[p * M_ALL + r];
        ssk += g_pk1[p * M_ALL + r];
    }
    const float qs = 1.0f / fmaxf(sqrtf(ssq), 1e-12f);
    g_qs[r] = qs;
    g_ks[r] = 1.0f / fmaxf(sqrtf(ssk), 1e-12f);
    g_a[r]  = sdw * qs * ATT_SCALE;
}

__global__ __launch_bounds__(256)
void softmax_kernel() {
    const int b = blockIdx.x;
    const int tid = threadIdx.x;
    __shared__ float sh[NTOK];
    __shared__ float red[8];
    __shared__ float stat[2];
    float m = -1e30f;
    for (int i = tid; i < NTOK; i += 256) {
        const float v = g_a[b * NTOK + i]; sh[i] = v; m = fmaxf(m, v);
    }
#pragma unroll
    for (int o = 16; o > 0; o >>= 1) m = fmaxf(m, __shfl_down_sync(0xffffffffu, m, o));
    if ((tid & 31) == 0) red[tid >> 5] = m;
    __syncthreads();
    if (tid == 0) {
        float mm = red[0];
        for (int i = 1; i < 8; i++) mm = fmaxf(mm, red[i]);
        stat[0] = mm;
    }
    __syncthreads();
    const float M = stat[0];
    float s = 0.f;
    for (int i = tid; i < NTOK; i += 256) {
        const float e = expf(sh[i] - M); sh[i] = e; s += e;
    }
#pragma unroll
    for (int o = 16; o > 0; o >>= 1) s += __shfl_down_sync(0xffffffffu, s, o);
    __syncthreads();
    if ((tid & 31) == 0) red[tid >> 5] = s;
    __syncthreads();
    if (tid == 0) {
        float t = 0.f;
        for (int i = 0; i < 8; i++) t += red[i];
        stat[1] = 1.0f / t;
    }
    __syncthreads();
    const float inv = stat[1];
    for (int i = tid; i < NTOK; i += 256) g_a[b * NTOK + i] = sh[i] * inv;
}

__global__ __launch_bounds__(256)
void gsum_kernel() {
    const int b = blockIdx.x;
    const int d = threadIdx.x * 2;
    float ax = 0.f, ay = 0.f;
    for (int n = blockIdx.y; n < NTOK; n += NSPLIT) {
        const int row = b * NTOK + n;
        const float w = g_a[row] * g_qs[row];
        const float2 qv = *(const float2*)(g_q + (size_t)row * DIM + d);
        ax += w * qv.x; ay += w * qv.y;
    }
    g_gp[(size_t)blockIdx.y * BATCH * DIM + b * DIM + d]     = ax;
    g_gp[(size_t)blockIdx.y * BATCH * DIM + b * DIM + d + 1] = ay;
}

__global__ __launch_bounds__(256)
void greduce_kernel() {
    const int i = blockIdx.x * 256 + threadIdx.x;
    float s = 0.f;
#pragma unroll
    for (int p = 0; p < NSPLIT; p++) s += g_gp[(size_t)p * BATCH * DIM + i];
    g_g[i] = s;
}

__global__ __launch_bounds__(256)
void ymul_kernel() {
    const int idx = blockIdx.x * 256 + threadIdx.x;
    const int m = idx >> 7, j = idx & 127;
    const int b = m / NVERT, t = m - b * NVERT;
    const int row = b * NTOK + t;
    const float ks = g_ks[row];
    const float4 kv = ((const float4*)g_k)[(size_t)row * 128 + j];
    const float4 gv = ((const float4*)g_g)[b * 128 + j];
    ((float4*)g_y)[idx] = make_float4(kv.x * gv.x * ks, kv.y * gv.y * ks,
                                      kv.z * gv.z * ks, kv.w * gv.w * ks);
}

// ---------------------------------------------------------------------------

extern "C" void kernel_launch(void* const* d_in, const int* in_sizes, int n_in,
                              void* d_out, int out_size) {
    const float* verts   = (const float*)d_in[0];
    const float* img_f   = (const float*)d_in[1];
    const float* fc_w    = (const float*)d_in[2];
    const float* fc_b    = (const float*)d_in[3];
    const float* q_w     = (const float*)d_in[4];
    const float* q_b     = (const float*)d_in[5];
    const float* k_w     = (const float*)d_in[6];
    const float* k_b     = (const float*)d_in[7];
    const float* w_g     = (const float*)d_in[8];
    const float* proj_w  = (const float*)d_in[9];
    const float* proj_b  = (const float*)d_in[10];
    const float* final_w = (const float*)d_in[11];
    const float* final_b = (const float*)d_in[12];
    float* out = (float*)d_out;

    float *pxi, *pq, *pk, *py, *po1, *pqs, *ppq1, *ppq2, *ppk1;
    cudaGetSymbolAddress((void**)&pxi,  g_xi);
    cudaGetSymbolAddress((void**)&pq,   g_q);
    cudaGetSymbolAddress((void**)&pk,   g_k);
    cudaGetSymbolAddress((void**)&py,   g_y);
    cudaGetSymbolAddress((void**)&po1,  g_o1);
    cudaGetSymbolAddress((void**)&pqs,  g_qs);
    cudaGetSymbolAddress((void**)&ppq1, g_pq1);
    cudaGetSymbolAddress((void**)&ppq2, g_pq2);
    cudaGetSymbolAddress((void**)&ppk1, g_pk1);

    cudaFuncSetAttribute(gemm_tc<0>, cudaFuncAttributeMaxDynamicSharedMemorySize, GEMM_SMEM);
    cudaFuncSetAttribute(gemm_tc<1>, cudaFuncAttributeMaxDynamicSharedMemorySize, GEMM_SMEM);
    cudaFuncSetAttribute(gemm_tc<2>, cudaFuncAttributeMaxDynamicSharedMemorySize, GEMM_SMEM);

    const RMap direct    = {1 << 30, 0, 0};
    const RMap vert_emap = {NVERT, NTOK, 0};

    // G1: img projection
    gemm_tc<0><<<dim3(DIM / BN, M_IMG / BM), 256, GEMM_SMEM>>>(
        img_f, nullptr, fc_w, fc_b, nullptr, nullptr, nullptr,
        pxi, nullptr, nullptr, IMGDIM, 0, direct, direct);
    // G2: q (+stats)
    gemm_tc<1><<<dim3(DIM / BN, M_ALL / BM), 256, GEMM_SMEM>>>(
        verts, pxi, q_w, q_b, nullptr, nullptr, w_g,
        pq, ppq1, ppq2, DIM, M_ALL, direct, direct);
    // G3: k (+stats)
    gemm_tc<2><<<dim3(DIM / BN, M_ALL / BM), 256, GEMM_SMEM>>>(
        verts, pxi, k_w, k_b, nullptr, nullptr, nullptr,
        pk, ppk1, nullptr, DIM, M_ALL, direct, direct);
    rowstat_lite_kernel<<<(M_ALL + 255) / 256, 256>>>();
    softmax_kernel<<<BATCH, 256>>>();
    gsum_kernel<<<dim3(BATCH, NSPLIT), 256>>>();
    greduce_kernel<<<(BATCH * DIM) / 256, 256>>>();
    ymul_kernel<<<(M_VRT * 128) / 256, 256>>>();
    // G4: proj + qs*q residual
    gemm_tc<0><<<dim3(DIM / BN, M_VRT / BM), 256, GEMM_SMEM>>>(
        py, nullptr, proj_w, proj_b, pq, pqs, nullptr,
        po1, nullptr, nullptr, DIM, 0, direct, vert_emap);
    // G5: final + verts residual
    gemm_tc<0><<<dim3(DIM / BN, M_VRT / BM), 256, GEMM_SMEM>>>(
        po1, nullptr, final_w, final_b, verts, nullptr, nullptr,
        out, nullptr, nullptr, DIM, 0, direct, direct);
}

// round 11
// speedup vs baseline: 2.3652x; 1.5277x over previous
#include <cuda_runtime.h>
#include <cuda_bf16.h>
#include <cstdint>

// ---------------------------------------------------------------------------
// img_attn: B=32, Nv=1556, Ni=256, N=1812 tokens, D=512, IMG_D=2048
//
//  C0 convert:  verts, img_f, 5 weight mats -> bf16 (round-to-nearest)
//  G1 gemm:  img_bf @ fc_wbf^T + fc_b          -> xi_bf (bf16 out)
//  G2 gemm:  split(verts_bf,xi_bf) @ q_w + q_b -> g_q fp32 (+stat partials)
//  G3 gemm:  split(verts_bf,xi_bf) @ k_w + k_b -> g_k fp32 (+stat partials)
//  K4 rowstat_lite; K5 softmax; K6 gsum+reduce; K7 ymul (-> y_bf)
//  G4 gemm:  y_bf @ proj_w + proj_b + qs*q -> o1_bf (bf16 out)
//  G5 gemm:  o1_bf @ final_w + final_b + verts -> out fp32
//
// GEMM: 128x128 CTA tile, 64x32 warp tile, bf16 m16n8k16 (fp32 accum),
// 3-stage cp.async pipeline, 256 threads, 2 CTAs/SM. K=64 bf16 per stage
// (128B rows, same smem geometry as the proven tf32 kernel).
// ---------------------------------------------------------------------------

#define BATCH 32
#define NVERT 1556
#define NIMG  256
#define NTOK  1812
#define DIM   512
#define IMGDIM 2048
#define M_ALL (BATCH * NTOK)    // 57984
#define M_VRT (BATCH * NVERT)   // 49792
#define M_IMG (BATCH * NIMG)    // 8192
#define ATT_SCALE 0.08838834764831845f
#define NSPLIT 16
#define NCT 4

typedef __nv_bfloat16 bf16;

__device__ __align__(256) float g_q [(size_t)M_ALL * DIM];
__device__ __align__(256) float g_k [(size_t)M_ALL * DIM];
__device__ __align__(256) float g_a [M_ALL];
__device__ __align__(256) float g_qs[M_ALL];
__device__ __align__(256) float g_ks[M_ALL];
__device__ __align__(256) float g_g [BATCH * DIM];
__device__ __align__(256) float g_gp[NSPLIT * BATCH * DIM];
__device__ __align__(256) float g_pq1[NCT * M_ALL];
__device__ __align__(256) float g_pq2[NCT * M_ALL];
__device__ __align__(256) float g_pk1[NCT * M_ALL];

__device__ __align__(256) bf16 g_vbf [(size_t)M_VRT * DIM];
__device__ __align__(256) bf16 g_ibf [(size_t)M_IMG * IMGDIM];
__device__ __align__(256) bf16 g_xibf[(size_t)M_IMG * DIM];
__device__ __align__(256) bf16 g_ybf [(size_t)M_VRT * DIM];
__device__ __align__(256) bf16 g_o1bf[(size_t)M_VRT * DIM];
__device__ __align__(256) bf16 g_wfc [(size_t)DIM * IMGDIM];
__device__ __align__(256) bf16 g_wq  [DIM * DIM];
__device__ __align__(256) bf16 g_wk  [DIM * DIM];
__device__ __align__(256) bf16 g_wpr [DIM * DIM];
__device__ __align__(256) bf16 g_wfn [DIM * DIM];

struct RMap { int div, stride, off; };
__device__ __forceinline__ int rmap_apply(const RMap m, int r) {
    int q = r / m.div;
    return q * m.stride + (r - q * m.div) + m.off;
}

__device__ __forceinline__ void mma_bf16(float* d, const uint32_t* a, const uint32_t* b) {
    asm volatile(
        "mma.sync.aligned.m16n8k16.row.col.f32.bf16.bf16.f32 "
        "{%0,%1,%2,%3},{%4,%5,%6,%7},{%8,%9},{%0,%1,%2,%3};"
        : "+f"(d[0]), "+f"(d[1]), "+f"(d[2]), "+f"(d[3])
        : "r"(a[0]), "r"(a[1]), "r"(a[2]), "r"(a[3]), "r"(b[0]), "r"(b[1]));
}

__device__ __forceinline__ uint32_t pack_bf2(float x, float y) {
    __nv_bfloat162 h = __float22bfloat162_rn(make_float2(x, y));
    return *reinterpret_cast<uint32_t*>(&h);
}

#define BM 128
#define BN 128
#define SSTR 36                                               // u32 units
#define STAGE_U32 ((BM + BN) * SSTR)                          // 9216
#define GEMM_SMEM (3 * STAGE_U32 * (int)sizeof(uint32_t))     // 110592 B

// MODE: 0 plain, 1 q-stats, 2 k-stats.  OUTBF: C stored bf16 (pairs) vs fp32
template<int MODE, int OUTBF>
__global__ __launch_bounds__(256, 2)
void gemm_bf(const bf16* __restrict__ A0, const bf16* __restrict__ A1,
             const bf16* __restrict__ Bw, const float* __restrict__ bias,
             const float* __restrict__ E, const float* __restrict__ escale,
             const float* __restrict__ wg,
             void* __restrict__ Cv, float* __restrict__ P1, float* __restrict__ P2,
             int K, int Mtot, RMap cmap, RMap emap)
{
    extern __shared__ uint32_t sm[];
    const int tid  = threadIdx.x;
    const int lane = tid & 31;
    const int warp = tid >> 5;
    const int wm   = warp >> 2;           // 0..1 -> 64 rows
    const int wn   = warp & 3;            // 0..3 -> 32 cols
    const long rowA0 = (long)blockIdx.y * BM;
    const long rowB0 = (long)blockIdx.x * BN;

    // A-row byte base pointers (two-source token split when A1 != null)
    const char* arow[4];
#pragma unroll
    for (int j = 0; j < 4; j++) {
        const int r = (tid + j * 256) >> 3;
        const long rr = rowA0 + r;
        if (A1) {
            const int b = (int)(rr / NTOK);
            const int t = (int)(rr - (long)b * NTOK);
            arow[j] = (const char*)((t < NVERT)
                        ? A0 + ((size_t)b * NVERT + t) * DIM
                        : A1 + ((size_t)b * NIMG + (t - NVERT)) * DIM);
        } else {
            arow[j] = (const char*)(A0 + rr * (size_t)K);
        }
    }

    float acc[4][4][4];
#pragma unroll
    for (int mt = 0; mt < 4; mt++)
#pragma unroll
        for (int nt = 0; nt < 4; nt++)
#pragma unroll
            for (int i = 0; i < 4; i++) acc[mt][nt][i] = 0.f;

    auto load_tiles = [&](int t) {
        uint32_t* As = sm + (t % 3) * STAGE_U32;
        uint32_t* Bs = As + BM * SSTR;
        const int kb = t * 128;                 // byte offset (64 bf16)
#pragma unroll
        for (int j = 0; j < 4; j++) {
            const int idx = tid + j * 256;
            const int r = idx >> 3;
            const int c16 = (idx & 7) << 4;     // 0..112 bytes
            {
                uint32_t sp = (uint32_t)__cvta_generic_to_shared(
                    As + r * SSTR + (c16 >> 2));
                asm volatile("cp.async.cg.shared.global [%0], [%1], 16;"
                             :: "r"(sp), "l"(arow[j] + kb + c16));
            }
            {
                const char* gb = (const char*)(Bw + (rowB0 + r) * (size_t)K) + kb + c16;
                uint32_t sp = (uint32_t)__cvta_generic_to_shared(
                    Bs + r * SSTR + (c16 >> 2));
                asm volatile("cp.async.cg.shared.global [%0], [%1], 16;"
                             :: "r"(sp), "l"(gb));
            }
        }
        asm volatile("cp.async.commit_group;" ::: "memory");
    };

    const int T = K / 64;
    load_tiles(0);
    load_tiles(1);

    for (int t = 0; t < T; t++) {
        if (t < T - 1) asm volatile("cp.async.wait_group 1;" ::: "memory");
        else           asm volatile("cp.async.wait_group 0;" ::: "memory");
        __syncthreads();
        if (t + 2 < T) load_tiles(t + 2);

        const uint32_t* Ab = sm + (t % 3) * STAGE_U32;
        const uint32_t* Bb = Ab + BM * SSTR;
#pragma unroll
        for (int ks = 0; ks < 4; ks++) {        // 4 x K=16 per stage
            const int kc = ks * 8 + (lane & 3);
            uint32_t af[4][4], bf[4][2];
#pragma unroll
            for (int mt = 0; mt < 4; mt++) {
                const int r = wm * 64 + mt * 16 + (lane >> 2);
                af[mt][0] = Ab[r * SSTR + kc];
                af[mt][1] = Ab[(r + 8) * SSTR + kc];
                af[mt][2] = Ab[r * SSTR + kc + 4];
                af[mt][3] = Ab[(r + 8) * SSTR + kc + 4];
            }
#pragma unroll
            for (int nt = 0; nt < 4; nt++) {
                const int n = wn * 32 + nt * 8 + (lane >> 2);
                bf[nt][0] = Bb[n * SSTR + kc];
                bf[nt][1] = Bb[n * SSTR + kc + 4];
            }
#pragma unroll
            for (int mt = 0; mt < 4; mt++)
#pragma unroll
                for (int nt = 0; nt < 4; nt++)
                    mma_bf16(acc[mt][nt], af[mt], bf[nt]);
        }
    }

    // ---- epilogue ----
    float st_sq0[4], st_sq1[4], st_dw0[4], st_dw1[4];

#pragma unroll
    for (int mt = 0; mt < 4; mt++) {
        const int gr0 = (int)rowA0 + wm * 64 + mt * 16 + (lane >> 2);
        const int gr1 = gr0 + 8;
        const int cr0 = rmap_apply(cmap, gr0);
        const int cr1 = rmap_apply(cmap, gr1);
        int er0 = 0, er1 = 0;
        float es0 = 1.f, es1 = 1.f;
        if (E) {
            er0 = rmap_apply(emap, gr0); er1 = rmap_apply(emap, gr1);
            if (escale) { es0 = escale[er0]; es1 = escale[er1]; }
        }
        float ssq0 = 0.f, ssq1 = 0.f, sdw0 = 0.f, sdw1 = 0.f;
#pragma unroll
        for (int nt = 0; nt < 4; nt++) {
            const int gc = (int)rowB0 + wn * 32 + nt * 8 + ((lane & 3) << 1);
            const float2 bb = *(const float2*)(bias + gc);
            float2 v0 = make_float2(acc[mt][nt][0] + bb.x, acc[mt][nt][1] + bb.y);
            float2 v1 = make_float2(acc[mt][nt][2] + bb.x, acc[mt][nt][3] + bb.y);
            if (E) {
                const float2 e0 = *(const float2*)(E + (size_t)er0 * DIM + gc);
                const float2 e1 = *(const float2*)(E + (size_t)er1 * DIM + gc);
                v0.x += es0 * e0.x; v0.y += es0 * e0.y;
                v1.x += es1 * e1.x; v1.y += es1 * e1.y;
            }
            if (OUTBF) {
                uint32_t* C = (uint32_t*)Cv;    // bf16 pairs, gc even
                C[((size_t)cr0 * DIM + gc) >> 1] = pack_bf2(v0.x, v0.y);
                C[((size_t)cr1 * DIM + gc) >> 1] = pack_bf2(v1.x, v1.y);
            } else {
                float* C = (float*)Cv;
                *(float2*)(C + (size_t)cr0 * DIM + gc) = v0;
                *(float2*)(C + (size_t)cr1 * DIM + gc) = v1;
            }
            if (MODE) {
                ssq0 += v0.x * v0.x + v0.y * v0.y;
                ssq1 += v1.x * v1.x + v1.y * v1.y;
                if (MODE == 1) {
                    const float2 w2 = *(const float2*)(wg + gc);
                    sdw0 += v0.x * w2.x + v0.y * w2.y;
                    sdw1 += v1.x * w2.x + v1.y * w2.y;
                }
            }
        }
        st_sq0[mt] = ssq0; st_sq1[mt] = ssq1;
        st_dw0[mt] = sdw0; st_dw1[mt] = sdw1;
    }

    if (MODE) {
        __syncthreads();
        float* s1 = (float*)sm;               // [128][4]
        float* s2 = (float*)sm + 128 * 4;
#pragma unroll
        for (int mt = 0; mt < 4; mt++) {
            float a0 = st_sq0[mt], a1 = st_sq1[mt];
            float b0 = st_dw0[mt], b1 = st_dw1[mt];
#pragma unroll
            for (int o = 1; o <= 2; o <<= 1) {
                a0 += __shfl_xor_sync(0xffffffffu, a0, o);
                a1 += __shfl_xor_sync(0xffffffffu, a1, o);
                if (MODE == 1) {
                    b0 += __shfl_xor_sync(0xffffffffu, b0, o);
                    b1 += __shfl_xor_sync(0xffffffffu, b1, o);
                }
            }
            if ((lane & 3) == 0) {
                const int r0 = wm * 64 + mt * 16 + (lane >> 2);
                const int r1 = r0 + 8;
                s1[r0 * 4 + wn] = a0; s1[r1 * 4 + wn] = a1;
                if (MODE == 1) { s2[r0 * 4 + wn] = b0; s2[r1 * 4 + wn] = b1; }
            }
        }
        __syncthreads();
        if (tid < 128) {
            const size_t dst = (size_t)blockIdx.x * Mtot + rowA0 + tid;
            P1[dst] = s1[tid * 4] + s1[tid * 4 + 1] + s1[tid * 4 + 2] + s1[tid * 4 + 3];
            if (MODE == 1)
                P2[dst] = s2[tid * 4] + s2[tid * 4 + 1] + s2[tid * 4 + 2] + s2[tid * 4 + 3];
        }
    }
}

// ---------------------------------------------------------------------------
// Small kernels
// ---------------------------------------------------------------------------

__global__ __launch_bounds__(256)
void cvt_bf16_kernel(const float4* __restrict__ src, uint2* __restrict__ dst, int n4) {
    const int i = blockIdx.x * 256 + threadIdx.x;
    if (i >= n4) return;
    const float4 v = src[i];
    dst[i] = make_uint2(pack_bf2(v.x, v.y), pack_bf2(v.z, v.w));
}

__global__ __launch_bounds__(256)
void rowstat_lite_kernel() {
    const int r = blockIdx.x * 256 + threadIdx.x;
    if (r >= M_ALL) return;
    float ssq = 0.f, sdw = 0.f, ssk = 0.f;
#pragma unroll
    for (int p = 0; p < NCT; p++) {
        ssq += g_pq1[p * M_ALL + r];
        sdw += g_pq2[p * M_ALL + r];
        ssk += g_pk1[p * M_ALL + r];
    }
    const float qs = 1.0f / fmaxf(sqrtf(ssq), 1e-12f);
    g_qs[r] = qs;
    g_ks[r] = 1.0f / fmaxf(sqrtf(ssk), 1e-12f);
    g_a[r]  = sdw * qs * ATT_SCALE;
}

__global__ __launch_bounds__(256)
void softmax_kernel() {
    const int b = blockIdx.x;
    const int tid = threadIdx.x;
    __shared__ float sh[NTOK];
    __shared__ float red[8];
    __shared__ float stat[2];
    float m = -1e30f;
    for (int i = tid; i < NTOK; i += 256) {
        const float v = g_a[b * NTOK + i]; sh[i] = v; m = fmaxf(m, v);
    }
#pragma unroll
    for (int o = 16; o > 0; o >>= 1) m = fmaxf(m, __shfl_down_sync(0xffffffffu, m, o));
    if ((tid & 31) == 0) red[tid >> 5] = m;
    __syncthreads();
    if (tid == 0) {
        float mm = red[0];
        for (int i = 1; i < 8; i++) mm = fmaxf(mm, red[i]);
        stat[0] = mm;
    }
    __syncthreads();
    const float M = stat[0];
    float s = 0.f;
    for (int i = tid; i < NTOK; i += 256) {
        const float e = expf(sh[i] - M); sh[i] = e; s += e;
    }
#pragma unroll
    for (int o = 16; o > 0; o >>= 1) s += __shfl_down_sync(0xffffffffu, s, o);
    __syncthreads();
    if ((tid & 31) == 0) red[tid >> 5] = s;
    __syncthreads();
    if (tid == 0) {
        float t = 0.f;
        for (int i = 0; i < 8; i++) t += red[i];
        stat[1] = 1.0f / t;
    }
    __syncthreads();
    const float inv = stat[1];
    for (int i = tid; i < NTOK; i += 256) g_a[b * NTOK + i] = sh[i] * inv;
}

__global__ __launch_bounds__(256)
void gsum_kernel() {
    const int b = blockIdx.x;
    const int d = threadIdx.x * 2;
    float ax = 0.f, ay = 0.f;
    for (int n = blockIdx.y; n < NTOK; n += NSPLIT) {
        const int row = b * NTOK + n;
        const float w = g_a[row] * g_qs[row];
        const float2 qv = *(const float2*)(g_q + (size_t)row * DIM + d);
        ax += w * qv.x; ay += w * qv.y;
    }
    g_gp[(size_t)blockIdx.y * BATCH * DIM + b * DIM + d]     = ax;
    g_gp[(size_t)blockIdx.y * BATCH * DIM + b * DIM + d + 1] = ay;
}

__global__ __launch_bounds__(256)
void greduce_kernel() {
    const int i = blockIdx.x * 256 + threadIdx.x;
    float s = 0.f;
#pragma unroll
    for (int p = 0; p < NSPLIT; p++) s += g_gp[(size_t)p * BATCH * DIM + i];
    g_g[i] = s;
}

// y_bf = bf16( g[b] * k * ks )   (vert rows only)
__global__ __launch_bounds__(256)
void ymul_kernel() {
    const int idx = blockIdx.x * 256 + threadIdx.x;   // < M_VRT*128
    const int m = idx >> 7, j = idx & 127;
    const int b = m / NVERT, t = m - b * NVERT;
    const int row = b * NTOK + t;
    const float ks = g_ks[row];
    const float4 kv = ((const float4*)g_k)[(size_t)row * 128 + j];
    const float4 gv = ((const float4*)g_g)[b * 128 + j];
    ((uint2*)g_ybf)[idx] = make_uint2(
        pack_bf2(kv.x * gv.x * ks, kv.y * gv.y * ks),
        pack_bf2(kv.z * gv.z * ks, kv.w * gv.w * ks));
}

// ---------------------------------------------------------------------------

extern "C" void kernel_launch(void* const* d_in, const int* in_sizes, int n_in,
                              void* d_out, int out_size) {
    const float* verts   = (const float*)d_in[0];
    const float* img_f   = (const float*)d_in[1];
    const float* fc_w    = (const float*)d_in[2];
    const float* fc_b    = (const float*)d_in[3];
    const float* q_w     = (const float*)d_in[4];
    const float* q_b     = (const float*)d_in[5];
    const float* k_w     = (const float*)d_in[6];
    const float* k_b     = (const float*)d_in[7];
    const float* w_g     = (const float*)d_in[8];
    const float* proj_w  = (const float*)d_in[9];
    const float* proj_b  = (const float*)d_in[10];
    const float* final_w = (const float*)d_in[11];
    const float* final_b = (const float*)d_in[12];
    float* out = (float*)d_out;

    float *pq, *pk, *pqs, *ppq1, *ppq2, *ppk1;
    bf16 *pvbf, *pibf, *pxibf, *pybf, *po1bf, *pwfc, *pwq, *pwk, *pwpr, *pwfn;
    cudaGetSymbolAddress((void**)&pq,    g_q);
    cudaGetSymbolAddress((void**)&pk,    g_k);
    cudaGetSymbolAddress((void**)&pqs,   g_qs);
    cudaGetSymbolAddress((void**)&ppq1,  g_pq1);
    cudaGetSymbolAddress((void**)&ppq2,  g_pq2);
    cudaGetSymbolAddress((void**)&ppk1,  g_pk1);
    cudaGetSymbolAddress((void**)&pvbf,  g_vbf);
    cudaGetSymbolAddress((void**)&pibf,  g_ibf);
    cudaGetSymbolAddress((void**)&pxibf, g_xibf);
    cudaGetSymbolAddress((void**)&pybf,  g_ybf);
    cudaGetSymbolAddress((void**)&po1bf, g_o1bf);
    cudaGetSymbolAddress((void**)&pwfc,  g_wfc);
    cudaGetSymbolAddress((void**)&pwq,   g_wq);
    cudaGetSymbolAddress((void**)&pwk,   g_wk);
    cudaGetSymbolAddress((void**)&pwpr,  g_wpr);
    cudaGetSymbolAddress((void**)&pwfn,  g_wfn);

    cudaFuncSetAttribute(gemm_bf<0,0>, cudaFuncAttributeMaxDynamicSharedMemorySize, GEMM_SMEM);
    cudaFuncSetAttribute(gemm_bf<0,1>, cudaFuncAttributeMaxDynamicSharedMemorySize, GEMM_SMEM);
    cudaFuncSetAttribute(gemm_bf<1,0>, cudaFuncAttributeMaxDynamicSharedMemorySize, GEMM_SMEM);
    cudaFuncSetAttribute(gemm_bf<2,0>, cudaFuncAttributeMaxDynamicSharedMemorySize, GEMM_SMEM);

    const RMap direct    = {1 << 30, 0, 0};
    const RMap vert_emap = {NVERT, NTOK, 0};

    // C0: fp32 -> bf16 conversions (round-to-nearest)
    auto cvt = [&](const float* s, bf16* d, size_t n) {
        const int n4 = (int)(n / 4);
        cvt_bf16_kernel<<<(n4 + 255) / 256, 256>>>((const float4*)s, (uint2*)d, n4);
    };
    cvt(verts,   pvbf, (size_t)M_VRT * DIM);
    cvt(img_f,   pibf, (size_t)M_IMG * IMGDIM);
    cvt(fc_w,    pwfc, (size_t)DIM * IMGDIM);
    cvt(q_w,     pwq,  (size_t)DIM * DIM);
    cvt(k_w,     pwk,  (size_t)DIM * DIM);
    cvt(proj_w,  pwpr, (size_t)DIM * DIM);
    cvt(final_w, pwfn, (size_t)DIM * DIM);

    // G1: img projection -> xi (bf16 out; only consumed as GEMM A input)
    gemm_bf<0,1><<<dim3(DIM / BN, M_IMG / BM), 256, GEMM_SMEM>>>(
        pibf, nullptr, pwfc, fc_b, nullptr, nullptr, nullptr,
        pxibf, nullptr, nullptr, IMGDIM, 0, direct, direct);
    // G2: q (+stats) fp32 out
    gemm_bf<1,0><<<dim3(DIM / BN, M_ALL / BM), 256, GEMM_SMEM>>>(
        pvbf, pxibf, pwq, q_b, nullptr, nullptr, w_g,
        pq, ppq1, ppq2, DIM, M_ALL, direct, direct);
    // G3: k (+stats) fp32 out
    gemm_bf<2,0><<<dim3(DIM / BN, M_ALL / BM), 256, GEMM_SMEM>>>(
        pvbf, pxibf, pwk, k_b, nullptr, nullptr, nullptr,
        pk, ppk1, nullptr, DIM, M_ALL, direct, direct);
    rowstat_lite_kernel<<<(M_ALL + 255) / 256, 256>>>();
    softmax_kernel<<<BATCH, 256>>>();
    gsum_kernel<<<dim3(BATCH, NSPLIT), 256>>>();
    greduce_kernel<<<(BATCH * DIM) / 256, 256>>>();
    ymul_kernel<<<(M_VRT * 128) / 256, 256>>>();
    // G4: proj + qs*q residual -> o1 (bf16 out; only consumed by G5)
    gemm_bf<0,1><<<dim3(DIM / BN, M_VRT / BM), 256, GEMM_SMEM>>>(
        pybf, nullptr, pwpr, proj_b, pq, pqs, nullptr,
        po1bf, nullptr, nullptr, DIM, 0, direct, vert_emap);
    // G5: final + verts residual -> out fp32
    gemm_bf<0,0><<<dim3(DIM / BN, M_VRT / BM), 256, GEMM_SMEM>>>(
        po1bf, nullptr, pwfn, final_b, verts, nullptr, nullptr,
        out, nullptr, nullptr, DIM, 0, direct, direct);
}

// round 12
// speedup vs baseline: 2.3677x; 1.0011x over previous
#include <cuda_runtime.h>
#include <cuda_bf16.h>
#include <cstdint>

// ---------------------------------------------------------------------------
// img_attn: B=32, Nv=1556, Ni=256, N=1812 tokens, D=512, IMG_D=2048
//
//  C0 convert (ONE fused kernel): verts, img_f, 5 weights -> bf16 (rn)
//  G1 gemm:  img_bf @ fc_wbf^T + fc_b          -> xi_bf (bf16 out)
//  G2 gemm:  split(verts_bf,xi_bf) @ q_w + q_b -> g_q fp32 (+stat partials)
//  G3 gemm:  split(verts_bf,xi_bf) @ k_w + k_b -> g_k fp32 (+stat partials)
//  K4 rowstat_lite; K5 softmax; K6 gsum+reduce; K7 ymul (-> y_bf)
//  G4 gemm:  y_bf @ proj_w + proj_b + qs*q -> o1_bf (bf16 out)
//  G5 gemm:  o1_bf @ final_w + final_b + verts -> out fp32
//
// GEMM: 128x128 CTA tile, 64x32 warp tile, bf16 m16n8k16 (fp32 accum),
// fragments loaded via ldmatrix.x4 (24 LDSM + 64 MMA per 64-K slab vs
// 96 LDS + 64 MMA), 3-stage cp.async, 256 threads, 2 CTAs/SM.
// ---------------------------------------------------------------------------

#define BATCH 32
#define NVERT 1556
#define NIMG  256
#define NTOK  1812
#define DIM   512
#define IMGDIM 2048
#define M_ALL (BATCH * NTOK)    // 57984
#define M_VRT (BATCH * NVERT)   // 49792
#define M_IMG (BATCH * NIMG)    // 8192
#define ATT_SCALE 0.08838834764831845f
#define NSPLIT 16
#define NCT 4

typedef __nv_bfloat16 bf16;

__device__ __align__(256) float g_q [(size_t)M_ALL * DIM];
__device__ __align__(256) float g_k [(size_t)M_ALL * DIM];
__device__ __align__(256) float g_a [M_ALL];
__device__ __align__(256) float g_qs[M_ALL];
__device__ __align__(256) float g_ks[M_ALL];
__device__ __align__(256) float g_g [BATCH * DIM];
__device__ __align__(256) float g_gp[NSPLIT * BATCH * DIM];
__device__ __align__(256) float g_pq1[NCT * M_ALL];
__device__ __align__(256) float g_pq2[NCT * M_ALL];
__device__ __align__(256) float g_pk1[NCT * M_ALL];

__device__ __align__(256) bf16 g_vbf [(size_t)M_VRT * DIM];
__device__ __align__(256) bf16 g_ibf [(size_t)M_IMG * IMGDIM];
__device__ __align__(256) bf16 g_xibf[(size_t)M_IMG * DIM];
__device__ __align__(256) bf16 g_ybf [(size_t)M_VRT * DIM];
__device__ __align__(256) bf16 g_o1bf[(size_t)M_VRT * DIM];
__device__ __align__(256) bf16 g_wfc [(size_t)DIM * IMGDIM];
__device__ __align__(256) bf16 g_wq  [DIM * DIM];
__device__ __align__(256) bf16 g_wk  [DIM * DIM];
__device__ __align__(256) bf16 g_wpr [DIM * DIM];
__device__ __align__(256) bf16 g_wfn [DIM * DIM];

struct RMap { int div, stride, off; };
__device__ __forceinline__ int rmap_apply(const RMap m, int r) {
    int q = r / m.div;
    return q * m.stride + (r - q * m.div) + m.off;
}

__device__ __forceinline__ void mma_bf16(float* d, const uint32_t* a, const uint32_t* b) {
    asm volatile(
        "mma.sync.aligned.m16n8k16.row.col.f32.bf16.bf16.f32 "
        "{%0,%1,%2,%3},{%4,%5,%6,%7},{%8,%9},{%0,%1,%2,%3};"
        : "+f"(d[0]), "+f"(d[1]), "+f"(d[2]), "+f"(d[3])
        : "r"(a[0]), "r"(a[1]), "r"(a[2]), "r"(a[3]), "r"(b[0]), "r"(b[1]));
}

#define LDSM4(r0, r1, r2, r3, addr) \
    asm volatile("ldmatrix.sync.aligned.m8n8.x4.shared.b16 {%0,%1,%2,%3}, [%4];" \
                 : "=r"(r0), "=r"(r1), "=r"(r2), "=r"(r3) : "r"(addr))

__device__ __forceinline__ uint32_t pack_bf2(float x, float y) {
    __nv_bfloat162 h = __float22bfloat162_rn(make_float2(x, y));
    return *reinterpret_cast<uint32_t*>(&h);
}

#define BM 128
#define BN 128
#define SSTR 36                                               // u32 units
#define ROWB (SSTR * 4)                                       // 144 bytes
#define STAGE_U32 ((BM + BN) * SSTR)                          // 9216
#define STAGE_BYTES (STAGE_U32 * 4)                           // 36864
#define B_OFF_BYTES (BM * ROWB)                               // 18432
#define GEMM_SMEM (3 * STAGE_BYTES)                           // 110592 B

// MODE: 0 plain, 1 q-stats, 2 k-stats.  OUTBF: C stored bf16 pairs vs fp32
template<int MODE, int OUTBF>
__global__ __launch_bounds__(256, 2)
void gemm_bf(const bf16* __restrict__ A0, const bf16* __restrict__ A1,
             const bf16* __restrict__ Bw, const float* __restrict__ bias,
             const float* __restrict__ E, const float* __restrict__ escale,
             const float* __restrict__ wg,
             void* __restrict__ Cv, float* __restrict__ P1, float* __restrict__ P2,
             int K, int Mtot, RMap cmap, RMap emap)
{
    extern __shared__ uint32_t sm[];
    const uint32_t smb = (uint32_t)__cvta_generic_to_shared(sm);
    const int tid  = threadIdx.x;
    const int lane = tid & 31;
    const int warp = tid >> 5;
    const int wm   = warp >> 2;           // 0..1 -> 64 rows
    const int wn   = warp & 3;            // 0..3 -> 32 cols
    const long rowA0 = (long)blockIdx.y * BM;
    const long rowB0 = (long)blockIdx.x * BN;

    // ldmatrix per-lane base offsets within a stage
    const uint32_t a_lo = (uint32_t)((wm * 64 + (lane & 15)) * ROWB + ((lane >> 4) << 4));
    const uint32_t b_lo = (uint32_t)(B_OFF_BYTES +
                          (wn * 32 + (lane & 15)) * ROWB + ((lane >> 4) << 4));

    // A-row byte base pointers (two-source token split when A1 != null)
    const char* arow[4];
#pragma unroll
    for (int j = 0; j < 4; j++) {
        const int r = (tid + j * 256) >> 3;
        const long rr = rowA0 + r;
        if (A1) {
            const int b = (int)(rr / NTOK);
            const int t = (int)(rr - (long)b * NTOK);
            arow[j] = (const char*)((t < NVERT)
                        ? A0 + ((size_t)b * NVERT + t) * DIM
                        : A1 + ((size_t)b * NIMG + (t - NVERT)) * DIM);
        } else {
            arow[j] = (const char*)(A0 + rr * (size_t)K);
        }
    }

    float acc[4][4][4];
#pragma unroll
    for (int mt = 0; mt < 4; mt++)
#pragma unroll
        for (int nt = 0; nt < 4; nt++)
#pragma unroll
            for (int i = 0; i < 4; i++) acc[mt][nt][i] = 0.f;

    auto load_tiles = [&](int t) {
        uint32_t* As = sm + (t % 3) * STAGE_U32;
        uint32_t* Bs = As + BM * SSTR;
        const int kb = t * 128;                 // byte offset (64 bf16)
#pragma unroll
        for (int j = 0; j < 4; j++) {
            const int idx = tid + j * 256;
            const int r = idx >> 3;
            const int c16 = (idx & 7) << 4;     // 0..112 bytes
            {
                uint32_t sp = (uint32_t)__cvta_generic_to_shared(
                    As + r * SSTR + (c16 >> 2));
                asm volatile("cp.async.cg.shared.global [%0], [%1], 16;"
                             :: "r"(sp), "l"(arow[j] + kb + c16));
            }
            {
                const char* gb = (const char*)(Bw + (rowB0 + r) * (size_t)K) + kb + c16;
                uint32_t sp = (uint32_t)__cvta_generic_to_shared(
                    Bs + r * SSTR + (c16 >> 2));
                asm volatile("cp.async.cg.shared.global [%0], [%1], 16;"
                             :: "r"(sp), "l"(gb));
            }
        }
        asm volatile("cp.async.commit_group;" ::: "memory");
    };

    const int T = K / 64;
    load_tiles(0);
    load_tiles(1);

    for (int t = 0; t < T; t++) {
        if (t < T - 1) asm volatile("cp.async.wait_group 1;" ::: "memory");
        else           asm volatile("cp.async.wait_group 0;" ::: "memory");
        __syncthreads();
        if (t + 2 < T) load_tiles(t + 2);

        const uint32_t sb = smb + (t % 3) * STAGE_BYTES;
        const uint32_t aaddr = sb + a_lo;
        const uint32_t baddr = sb + b_lo;
#pragma unroll
        for (int ks = 0; ks < 4; ks++) {        // 4 x K=16 per stage
            const uint32_t koff = ks * 32;      // 16 bf16 = 32 bytes
            uint32_t af[4][4], bf[4][2];
#pragma unroll
            for (int mt = 0; mt < 4; mt++)
                LDSM4(af[mt][0], af[mt][1], af[mt][2], af[mt][3],
                      aaddr + mt * (16 * ROWB) + koff);
#pragma unroll
            for (int np = 0; np < 2; np++)
                LDSM4(bf[2 * np][0], bf[2 * np + 1][0], bf[2 * np][1], bf[2 * np + 1][1],
                      baddr + np * (16 * ROWB) + koff);
#pragma unroll
            for (int mt = 0; mt < 4; mt++)
#pragma unroll
                for (int nt = 0; nt < 4; nt++)
                    mma_bf16(acc[mt][nt], af[mt], bf[nt]);
        }
    }

    // ---- epilogue ----
    float st_sq0[4], st_sq1[4], st_dw0[4], st_dw1[4];

#pragma unroll
    for (int mt = 0; mt < 4; mt++) {
        const int gr0 = (int)rowA0 + wm * 64 + mt * 16 + (lane >> 2);
        const int gr1 = gr0 + 8;
        const int cr0 = rmap_apply(cmap, gr0);
        const int cr1 = rmap_apply(cmap, gr1);
        int er0 = 0, er1 = 0;
        float es0 = 1.f, es1 = 1.f;
        if (E) {
            er0 = rmap_apply(emap, gr0); er1 = rmap_apply(emap, gr1);
            if (escale) { es0 = escale[er0]; es1 = escale[er1]; }
        }
        float ssq0 = 0.f, ssq1 = 0.f, sdw0 = 0.f, sdw1 = 0.f;
#pragma unroll
        for (int nt = 0; nt < 4; nt++) {
            const int gc = (int)rowB0 + wn * 32 + nt * 8 + ((lane & 3) << 1);
            const float2 bb = *(const float2*)(bias + gc);
            float2 v0 = make_float2(acc[mt][nt][0] + bb.x, acc[mt][nt][1] + bb.y);
            float2 v1 = make_float2(acc[mt][nt][2] + bb.x, acc[mt][nt][3] + bb.y);
            if (E) {
                const float2 e0 = *(const float2*)(E + (size_t)er0 * DIM + gc);
                const float2 e1 = *(const float2*)(E + (size_t)er1 * DIM + gc);
                v0.x += es0 * e0.x; v0.y += es0 * e0.y;
                v1.x += es1 * e1.x; v1.y += es1 * e1.y;
            }
            if (OUTBF) {
                uint32_t* C = (uint32_t*)Cv;    // bf16 pairs, gc even
                C[((size_t)cr0 * DIM + gc) >> 1] = pack_bf2(v0.x, v0.y);
                C[((size_t)cr1 * DIM + gc) >> 1] = pack_bf2(v1.x, v1.y);
            } else {
                float* C = (float*)Cv;
                *(float2*)(C + (size_t)cr0 * DIM + gc) = v0;
                *(float2*)(C + (size_t)cr1 * DIM + gc) = v1;
            }
            if (MODE) {
                ssq0 += v0.x * v0.x + v0.y * v0.y;
                ssq1 += v1.x * v1.x + v1.y * v1.y;
                if (MODE == 1) {
                    const float2 w2 = *(const float2*)(wg + gc);
                    sdw0 += v0.x * w2.x + v0.y * w2.y;
                    sdw1 += v1.x * w2.x + v1.y * w2.y;
                }
            }
        }
        st_sq0[mt] = ssq0; st_sq1[mt] = ssq1;
        st_dw0[mt] = sdw0; st_dw1[mt] = sdw1;
    }

    if (MODE) {
        __syncthreads();
        float* s1 = (float*)sm;               // [128][4]
        float* s2 = (float*)sm + 128 * 4;
#pragma unroll
        for (int mt = 0; mt < 4; mt++) {
            float a0 = st_sq0[mt], a1 = st_sq1[mt];
            float b0 = st_dw0[mt], b1 = st_dw1[mt];
#pragma unroll
            for (int o = 1; o <= 2; o <<= 1) {
                a0 += __shfl_xor_sync(0xffffffffu, a0, o);
                a1 += __shfl_xor_sync(0xffffffffu, a1, o);
                if (MODE == 1) {
                    b0 += __shfl_xor_sync(0xffffffffu, b0, o);
                    b1 += __shfl_xor_sync(0xffffffffu, b1, o);
                }
            }
            if ((lane & 3) == 0) {
                const int r0 = wm * 64 + mt * 16 + (lane >> 2);
                const int r1 = r0 + 8;
                s1[r0 * 4 + wn] = a0; s1[r1 * 4 + wn] = a1;
                if (MODE == 1) { s2[r0 * 4 + wn] = b0; s2[r1 * 4 + wn] = b1; }
            }
        }
        __syncthreads();
        if (tid < 128) {
            const size_t dst = (size_t)blockIdx.x * Mtot + rowA0 + tid;
            P1[dst] = s1[tid * 4] + s1[tid * 4 + 1] + s1[tid * 4 + 2] + s1[tid * 4 + 3];
            if (MODE == 1)
                P2[dst] = s2[tid * 4] + s2[tid * 4 + 1] + s2[tid * 4 + 2] + s2[tid * 4 + 3];
        }
    }
}

// ---------------------------------------------------------------------------
// Small kernels
// ---------------------------------------------------------------------------

#define N4_V   (M_VRT * 128)            // M_VRT*DIM/4  = 6373376
#define N4_I   ((M_IMG / 4) * IMGDIM)   // M_IMG*IMGDIM/4 = 4194304
#define N4_WFC (DIM * IMGDIM / 4)       // 262144
#define N4_W   (DIM * DIM / 4)          // 65536
#define N4_TOTAL (N4_V + N4_I + N4_WFC + 4 * N4_W)   // 11091968

// one fused fp32 -> bf16 convert across all 7 arrays
__global__ __launch_bounds__(256)
void cvt_all_kernel(const float4* __restrict__ v,  const float4* __restrict__ im,
                    const float4* __restrict__ wfc, const float4* __restrict__ wq,
                    const float4* __restrict__ wk,  const float4* __restrict__ wpr,
                    const float4* __restrict__ wfn)
{
    long i = (long)blockIdx.x * 256 + threadIdx.x;
    const float4* s; uint2* d;
    if (i < N4_V)                   { s = v;   d = (uint2*)g_vbf; }
    else if ((i -= N4_V)   < N4_I)  { s = im;  d = (uint2*)g_ibf; }
    else if ((i -= N4_I)   < N4_WFC){ s = wfc; d = (uint2*)g_wfc; }
    else if ((i -= N4_WFC) < N4_W)  { s = wq;  d = (uint2*)g_wq;  }
    else if ((i -= N4_W)   < N4_W)  { s = wk;  d = (uint2*)g_wk;  }
    else if ((i -= N4_W)   < N4_W)  { s = wpr; d = (uint2*)g_wpr; }
    else if ((i -= N4_W)   < N4_W)  { s = wfn; d = (uint2*)g_wfn; }
    else return;
    const float4 x = s[i];
    d[i] = make_uint2(pack_bf2(x.x, x.y), pack_bf2(x.z, x.w));
}

__global__ __launch_bounds__(256)
void rowstat_lite_kernel() {
    const int r = blockIdx.x * 256 + threadIdx.x;
    if (r >= M_ALL) return;
    float ssq = 0.f, sdw = 0.f, ssk = 0.f;
#pragma unroll
    for (int p = 0; p < NCT; p++) {
        ssq += g_pq1[p * M_ALL + r];
        sdw += g_pq2[p * M_ALL + r];
        ssk += g_pk1[p * M_ALL + r];
    }
    const float qs = 1.0f / fmaxf(sqrtf(ssq), 1e-12f);
    g_qs[r] = qs;
    g_ks[r] = 1.0f / fmaxf(sqrtf(ssk), 1e-12f);
    g_a[r]  = sdw * qs * ATT_SCALE;
}

__global__ __launch_bounds__(256)
void softmax_kernel() {
    const int b = blockIdx.x;
    const int tid = threadIdx.x;
    __shared__ float sh[NTOK];
    __shared__ float red[8];
    __shared__ float stat[2];
    float m = -1e30f;
    for (int i = tid; i < NTOK; i += 256) {
        const float v = g_a[b * NTOK + i]; sh[i] = v; m = fmaxf(m, v);
    }
#pragma unroll
    for (int o = 16; o > 0; o >>= 1) m = fmaxf(m, __shfl_down_sync(0xffffffffu, m, o));
    if ((tid & 31) == 0) red[tid >> 5] = m;
    __syncthreads();
    if (tid == 0) {
        float mm = red[0];
        for (int i = 1; i < 8; i++) mm = fmaxf(mm, red[i]);
        stat[0] = mm;
    }
    __syncthreads();
    const float M = stat[0];
    float s = 0.f;
    for (int i = tid; i < NTOK; i += 256) {
        const float e = expf(sh[i] - M); sh[i] = e; s += e;
    }
#pragma unroll
    for (int o = 16; o > 0; o >>= 1) s += __shfl_down_sync(0xffffffffu, s, o);
    __syncthreads();
    if ((tid & 31) == 0) red[tid >> 5] = s;
    __syncthreads();
    if (tid == 0) {
        float t = 0.f;
        for (int i = 0; i < 8; i++) t += red[i];
        stat[1] = 1.0f / t;
    }
    __syncthreads();
    const float inv = stat[1];
    for (int i = tid; i < NTOK; i += 256) g_a[b * NTOK + i] = sh[i] * inv;
}

__global__ __launch_bounds__(256)
void gsum_kernel() {
    const int b = blockIdx.x;
    const int d = threadIdx.x * 2;
    float ax = 0.f, ay = 0.f;
    for (int n = blockIdx.y; n < NTOK; n += NSPLIT) {
        const int row = b * NTOK + n;
        const float w = g_a[row] * g_qs[row];
        const float2 qv = *(const float2*)(g_q + (size_t)row * DIM + d);
        ax += w * qv.x; ay += w * qv.y;
    }
    g_gp[(size_t)blockIdx.y * BATCH * DIM + b * DIM + d]     = ax;
    g_gp[(size_t)blockIdx.y * BATCH * DIM + b * DIM + d + 1] = ay;
}

__global__ __launch_bounds__(256)
void greduce_kernel() {
    const int i = blockIdx.x * 256 + threadIdx.x;
    float s = 0.f;
#pragma unroll
    for (int p = 0; p < NSPLIT; p++) s += g_gp[(size_t)p * BATCH * DIM + i];
    g_g[i] = s;
}

// y_bf = bf16( g[b] * k * ks )   (vert rows only)
__global__ __launch_bounds__(256)
void ymul_kernel() {
    const int idx = blockIdx.x * 256 + threadIdx.x;   // < M_VRT*128
    const int m = idx >> 7, j = idx & 127;
    const int b = m / NVERT, t = m - b * NVERT;
    const int row = b * NTOK + t;
    const float ks = g_ks[row];
    const float4 kv = ((const float4*)g_k)[(size_t)row * 128 + j];
    const float4 gv = ((const float4*)g_g)[b * 128 + j];
    ((uint2*)g_ybf)[idx] = make_uint2(
        pack_bf2(kv.x * gv.x * ks, kv.y * gv.y * ks),
        pack_bf2(kv.z * gv.z * ks, kv.w * gv.w * ks));
}

// ---------------------------------------------------------------------------

extern "C" void kernel_launch(void* const* d_in, const int* in_sizes, int n_in,
                              void* d_out, int out_size) {
    const float* verts   = (const float*)d_in[0];
    const float* img_f   = (const float*)d_in[1];
    const float* fc_w    = (const float*)d_in[2];
    const float* fc_b    = (const float*)d_in[3];
    const float* q_w     = (const float*)d_in[4];
    const float* q_b     = (const float*)d_in[5];
    const float* k_w     = (const float*)d_in[6];
    const float* k_b     = (const float*)d_in[7];
    const float* w_g     = (const float*)d_in[8];
    const float* proj_w  = (const float*)d_in[9];
    const float* proj_b  = (const float*)d_in[10];
    const float* final_w = (const float*)d_in[11];
    const float* final_b = (const float*)d_in[12];
    float* out = (float*)d_out;

    float *pq, *pk, *pqs, *ppq1, *ppq2, *ppk1;
    bf16 *pvbf, *pxibf, *pybf, *po1bf, *pwfc, *pwq, *pwk, *pwpr, *pwfn, *pibf;
    cudaGetSymbolAddress((void**)&pq,    g_q);
    cudaGetSymbolAddress((void**)&pk,    g_k);
    cudaGetSymbolAddress((void**)&pqs,   g_qs);
    cudaGetSymbolAddress((void**)&ppq1,  g_pq1);
    cudaGetSymbolAddress((void**)&ppq2,  g_pq2);
    cudaGetSymbolAddress((void**)&ppk1,  g_pk1);
    cudaGetSymbolAddress((void**)&pvbf,  g_vbf);
    cudaGetSymbolAddress((void**)&pibf,  g_ibf);
    cudaGetSymbolAddress((void**)&pxibf, g_xibf);
    cudaGetSymbolAddress((void**)&pybf,  g_ybf);
    cudaGetSymbolAddress((void**)&po1bf, g_o1bf);
    cudaGetSymbolAddress((void**)&pwfc,  g_wfc);
    cudaGetSymbolAddress((void**)&pwq,   g_wq);
    cudaGetSymbolAddress((void**)&pwk,   g_wk);
    cudaGetSymbolAddress((void**)&pwpr,  g_wpr);
    cudaGetSymbolAddress((void**)&pwfn,  g_wfn);

    cudaFuncSetAttribute(gemm_bf<0,0>, cudaFuncAttributeMaxDynamicSharedMemorySize, GEMM_SMEM);
    cudaFuncSetAttribute(gemm_bf<0,1>, cudaFuncAttributeMaxDynamicSharedMemorySize, GEMM_SMEM);
    cudaFuncSetAttribute(gemm_bf<1,0>, cudaFuncAttributeMaxDynamicSharedMemorySize, GEMM_SMEM);
    cudaFuncSetAttribute(gemm_bf<2,0>, cudaFuncAttributeMaxDynamicSharedMemorySize, GEMM_SMEM);

    const RMap direct    = {1 << 30, 0, 0};
    const RMap vert_emap = {NVERT, NTOK, 0};

    // C0: single fused fp32 -> bf16 convert
    cvt_all_kernel<<<N4_TOTAL / 256, 256>>>(
        (const float4*)verts, (const float4*)img_f, (const float4*)fc_w,
        (const float4*)q_w, (const float4*)k_w, (const float4*)proj_w,
        (const float4*)final_w);

    // G1: img projection -> xi (bf16 out)
    gemm_bf<0,1><<<dim3(DIM / BN, M_IMG / BM), 256, GEMM_SMEM>>>(
        pibf, nullptr, pwfc, fc_b, nullptr, nullptr, nullptr,
        pxibf, nullptr, nullptr, IMGDIM, 0, direct, direct);
    // G2: q (+stats) fp32 out
    gemm_bf<1,0><<<dim3(DIM / BN, M_ALL / BM), 256, GEMM_SMEM>>>(
        pvbf, pxibf, pwq, q_b, nullptr, nullptr, w_g,
        pq, ppq1, ppq2, DIM, M_ALL, direct, direct);
    // G3: k (+stats) fp32 out
    gemm_bf<2,0><<<dim3(DIM / BN, M_ALL / BM), 256, GEMM_SMEM>>>(
        pvbf, pxibf, pwk, k_b, nullptr, nullptr, nullptr,
        pk, ppk1, nullptr, DIM, M_ALL, direct, direct);
    rowstat_lite_kernel<<<(M_ALL + 255) / 256, 256>>>();
    softmax_kernel<<<BATCH, 256>>>();
    gsum_kernel<<<dim3(BATCH, NSPLIT), 256>>>();
    greduce_kernel<<<(BATCH * DIM) / 256, 256>>>();
    ymul_kernel<<<(M_VRT * 128) / 256, 256>>>();
    // G4: proj + qs*q residual -> o1 (bf16 out)
    gemm_bf<0,1><<<dim3(DIM / BN, M_VRT / BM), 256, GEMM_SMEM>>>(
        pybf, nullptr, pwpr, proj_b, pq, pqs, nullptr,
        po1bf, nullptr, nullptr, DIM, 0, direct, vert_emap);
    // G5: final + verts residual -> out fp32
    gemm_bf<0,0><<<dim3(DIM / BN, M_VRT / BM), 256, GEMM_SMEM>>>(
        po1bf, nullptr, pwfn, final_b, verts, nullptr, nullptr,
        out, nullptr, nullptr, DIM, 0, direct, direct);
}

// round 15
// speedup vs baseline: 2.5378x; 1.0718x over previous
#include <cuda_runtime.h>
#include <cuda_bf16.h>
#include <cstdint>

// ---------------------------------------------------------------------------
// img_attn: B=32, Nv=1556, Ni=256, N=1812 tokens, D=512, IMG_D=2048
//
//  C0 convert (one fused kernel): verts, img_f, 5 weights -> bf16 (rn)
//  G1 gemm:   img_bf @ fc_wbf^T + fc_b            -> xi_bf        (K=2048)
//  G23 gemm:  split(verts_bf,xi_bf) @ {q_w,k_w}   -> g_q,g_k      (grid.z=2,
//             fused q/k launch, + row-stat partials in epilogue)
//  K4 rowstat_lite; K5 softmax; K6 gsum+reduce; K7 ymul (-> y_bf)
//  G4 gemm:   y_bf @ proj_w + proj_b + qs*q  -> o1_bf
//  G5 gemm:   o1_bf @ final_w + final_b + verts -> out fp32
//
// GEMM: 128x128 CTA tile, 64x32 warp tile, bf16 m16n8k16 (fp32 accum),
// ldmatrix.x4 fragments, COMPILE-TIME K with unrolled mainloop (immediate
// addressing, near-zero ALU), 2-stage cp.async, 256 threads, 2 CTAs/SM.
// ---------------------------------------------------------------------------

#define BATCH 32
#define NVERT 1556
#define NIMG  256
#define NTOK  1812
#define DIM   512
#define IMGDIM 2048
#define M_ALL (BATCH * NTOK)    // 57984
#define M_VRT (BATCH * NVERT)   // 49792
#define M_IMG (BATCH * NIMG)    // 8192
#define ATT_SCALE 0.08838834764831845f
#define NSPLIT 16
#define NCT 4

typedef __nv_bfloat16 bf16;

__device__ __align__(256) float g_q [(size_t)M_ALL * DIM];
__device__ __align__(256) float g_k [(size_t)M_ALL * DIM];
__device__ __align__(256) float g_a [M_ALL];
__device__ __align__(256) float g_qs[M_ALL];
__device__ __align__(256) float g_ks[M_ALL];
__device__ __align__(256) float g_g [BATCH * DIM];
__device__ __align__(256) float g_gp[NSPLIT * BATCH * DIM];
__device__ __align__(256) float g_pq1[NCT * M_ALL];
__device__ __align__(256) float g_pq2[NCT * M_ALL];
__device__ __align__(256) float g_pk1[NCT * M_ALL];

__device__ __align__(256) bf16 g_vbf [(size_t)M_VRT * DIM];
__device__ __align__(256) bf16 g_ibf [(size_t)M_IMG * IMGDIM];
__device__ __align__(256) bf16 g_xibf[(size_t)M_IMG * DIM];
__device__ __align__(256) bf16 g_ybf [(size_t)M_VRT * DIM];
__device__ __align__(256) bf16 g_o1bf[(size_t)M_VRT * DIM];
__device__ __align__(256) bf16 g_wfc [(size_t)DIM * IMGDIM];
__device__ __align__(256) bf16 g_wq  [DIM * DIM];
__device__ __align__(256) bf16 g_wk  [DIM * DIM];
__device__ __align__(256) bf16 g_wpr [DIM * DIM];
__device__ __align__(256) bf16 g_wfn [DIM * DIM];

struct RMap { int div, stride, off; };
__device__ __forceinline__ int rmap_apply(const RMap m, int r) {
    int q = r / m.div;
    return q * m.stride + (r - q * m.div) + m.off;
}

__device__ __forceinline__ void mma_bf16(float* d, const uint32_t* a, const uint32_t* b) {
    asm volatile(
        "mma.sync.aligned.m16n8k16.row.col.f32.bf16.bf16.f32 "
        "{%0,%1,%2,%3},{%4,%5,%6,%7},{%8,%9},{%0,%1,%2,%3};"
        : "+f"(d[0]), "+f"(d[1]), "+f"(d[2]), "+f"(d[3])
        : "r"(a[0]), "r"(a[1]), "r"(a[2]), "r"(a[3]), "r"(b[0]), "r"(b[1]));
}

#define LDSM4(r0, r1, r2, r3, addr) \
    asm volatile("ldmatrix.sync.aligned.m8n8.x4.shared.b16 {%0,%1,%2,%3}, [%4];" \
                 : "=r"(r0), "=r"(r1), "=r"(r2), "=r"(r3) : "r"(addr))

__device__ __forceinline__ uint32_t pack_bf2(float x, float y) {
    __nv_bfloat162 h = __float22bfloat162_rn(make_float2(x, y));
    return *reinterpret_cast<uint32_t*>(&h);
}

#define BM 128
#define BN 128
#define ROWB 144                                  // 36 u32 = 144 B row stride
#define STAGE_BYTES ((BM + BN) * ROWB)            // 36864
#define B_OFF_BYTES (BM * ROWB)                   // 18432
#define GEMM_SMEM (2 * STAGE_BYTES)               // 73728 B

// K compile-time; STATS: epilogue row stats (z==0 adds wg-dot); OUTBF: bf16 C.
// When STATS, gridDim.z=2 selects (BwA,biasA,CvA,P1A) vs (BwB,biasB,CvB,P1B).
template<int K, int STATS, int OUTBF>
__global__ __launch_bounds__(256, 2)
void gemm_bf(const bf16* __restrict__ A0, const bf16* __restrict__ A1,
             const bf16* __restrict__ BwA, const bf16* __restrict__ BwB,
             const float* __restrict__ biasA, const float* __restrict__ biasB,
             const float* __restrict__ E, const float* __restrict__ escale,
             const float* __restrict__ wg,
             void* __restrict__ CvA, void* __restrict__ CvB,
             float* __restrict__ P1A, float* __restrict__ P1B,
             float* __restrict__ P2,
             int Mtot, RMap cmap, RMap emap)
{
    extern __shared__ uint32_t sm[];
    const uint32_t smb = (uint32_t)__cvta_generic_to_shared(sm);
    const int tid  = threadIdx.x;
    const int lane = tid & 31;
    const int warp = tid >> 5;
    const int wm   = warp >> 2;           // 0..1 -> 64 rows
    const int wn   = warp & 3;            // 0..3 -> 32 cols
    const int z    = STATS ? (int)blockIdx.z : 0;
    const long rowA0 = (long)blockIdx.y * BM;
    const long rowB0 = (long)blockIdx.x * BN;

    const bf16*  Bw   = z ? BwB   : BwA;
    const float* bias = z ? biasB : biasA;
    void*        Cv   = z ? CvB   : CvA;
    float*       P1   = z ? P1B   : P1A;

    // ldmatrix per-lane base offsets within a stage
    const uint32_t a_lo = (uint32_t)((wm * 64 + (lane & 15)) * ROWB + ((lane >> 4) << 4));
    const uint32_t b_lo = (uint32_t)(B_OFF_BYTES +
                          (wn * 32 + (lane & 15)) * ROWB + ((lane >> 4) << 4));

    // per-thread cp.async src pointers and smem dst addresses
    const char* pa[4]; const char* pb[4];
    uint32_t da[4], db[4];
#pragma unroll
    for (int j = 0; j < 4; j++) {
        const int idx = tid + j * 256;
        const int r   = idx >> 3;
        const int c16 = (idx & 7) << 4;
        const long rr = rowA0 + r;
        const bf16* abase;
        if (A1) {
            const int b = (int)(rr / NTOK);
            const int t = (int)(rr - (long)b * NTOK);
            abase = (t < NVERT) ? A0 + ((size_t)b * NVERT + t) * DIM
                                : A1 + ((size_t)b * NIMG + (t - NVERT)) * DIM;
        } else {
            abase = A0 + rr * (size_t)K;
        }
        pa[j] = (const char*)abase + c16;
        pb[j] = (const char*)(Bw + (rowB0 + r) * (size_t)K) + c16;
        da[j] = smb + r * ROWB + c16;
        db[j] = smb + B_OFF_BYTES + r * ROWB + c16;
    }

    float acc[4][4][4];
#pragma unroll
    for (int mt = 0; mt < 4; mt++)
#pragma unroll
        for (int nt = 0; nt < 4; nt++)
#pragma unroll
            for (int i = 0; i < 4; i++) acc[mt][nt][i] = 0.f;

    constexpr int T = K / 64;

    auto load_stage = [&](int t) {
        const uint32_t soff = (uint32_t)(t & 1) * STAGE_BYTES;
        const int kb = t * 128;
#pragma unroll
        for (int j = 0; j < 4; j++) {
            asm volatile("cp.async.cg.shared.global [%0], [%1], 16;"
                         :: "r"(da[j] + soff), "l"(pa[j] + kb));
            asm volatile("cp.async.cg.shared.global [%0], [%1], 16;"
                         :: "r"(db[j] + soff), "l"(pb[j] + kb));
        }
        asm volatile("cp.async.commit_group;" ::: "memory");
    };

    auto compute_stage = [&](int t) {
        const uint32_t soff  = (uint32_t)(t & 1) * STAGE_BYTES;
        const uint32_t aaddr = smb + soff + a_lo;
        const uint32_t baddr = smb + soff + b_lo;
#pragma unroll
        for (int ks = 0; ks < 4; ks++) {
            const uint32_t koff = ks * 32;
            uint32_t af[4][4], bf[4][2];
#pragma unroll
            for (int mt = 0; mt < 4; mt++)
                LDSM4(af[mt][0], af[mt][1], af[mt][2], af[mt][3],
                      aaddr + mt * (16 * ROWB) + koff);
#pragma unroll
            for (int np = 0; np < 2; np++)
                LDSM4(bf[2 * np][0], bf[2 * np + 1][0], bf[2 * np][1], bf[2 * np + 1][1],
                      baddr + np * (16 * ROWB) + koff);
#pragma unroll
            for (int mt = 0; mt < 4; mt++)
#pragma unroll
                for (int nt = 0; nt < 4; nt++)
                    mma_bf16(acc[mt][nt], af[mt], bf[nt]);
        }
    };

    load_stage(0);
    if constexpr (K == 512) {
#pragma unroll
        for (int t = 0; t < T; t++) {
            asm volatile("cp.async.wait_group 0;" ::: "memory");
            __syncthreads();
            if (t + 1 < T) load_stage(t + 1);
            compute_stage(t);
        }
    } else {
#pragma unroll 2
        for (int t = 0; t < T; t++) {
            asm volatile("cp.async.wait_group 0;" ::: "memory");
            __syncthreads();
            if (t + 1 < T) load_stage(t + 1);
            compute_stage(t);
        }
    }

    // ---- epilogue: bias (+ escale*E), optional row-stat partials ----
    float st_sq0[4], st_sq1[4], st_dw0[4], st_dw1[4];

#pragma unroll
    for (int mt = 0; mt < 4; mt++) {
        const int gr0 = (int)rowA0 + wm * 64 + mt * 16 + (lane >> 2);
        const int gr1 = gr0 + 8;
        const int cr0 = rmap_apply(cmap, gr0);
        const int cr1 = rmap_apply(cmap, gr1);
        int er0 = 0, er1 = 0;
        float es0 = 1.f, es1 = 1.f;
        if (E) {
            er0 = rmap_apply(emap, gr0); er1 = rmap_apply(emap, gr1);
            if (escale) { es0 = escale[er0]; es1 = escale[er1]; }
        }
        float ssq0 = 0.f, ssq1 = 0.f, sdw0 = 0.f, sdw1 = 0.f;
#pragma unroll
        for (int nt = 0; nt < 4; nt++) {
            const int gc = (int)rowB0 + wn * 32 + nt * 8 + ((lane & 3) << 1);
            const float2 bb = *(const float2*)(bias + gc);
            float2 v0 = make_float2(acc[mt][nt][0] + bb.x, acc[mt][nt][1] + bb.y);
            float2 v1 = make_float2(acc[mt][nt][2] + bb.x, acc[mt][nt][3] + bb.y);
            if (E) {
                const float2 e0 = *(const float2*)(E + (size_t)er0 * DIM + gc);
                const float2 e1 = *(const float2*)(E + (size_t)er1 * DIM + gc);
                v0.x += es0 * e0.x; v0.y += es0 * e0.y;
                v1.x += es1 * e1.x; v1.y += es1 * e1.y;
            }
            if (OUTBF) {
                uint32_t* C = (uint32_t*)Cv;    // bf16 pairs, gc even
                C[((size_t)cr0 * DIM + gc) >> 1] = pack_bf2(v0.x, v0.y);
                C[((size_t)cr1 * DIM + gc) >> 1] = pack_bf2(v1.x, v1.y);
            } else {
                float* C = (float*)Cv;
                *(float2*)(C + (size_t)cr0 * DIM + gc) = v0;
                *(float2*)(C + (size_t)cr1 * DIM + gc) = v1;
            }
            if (STATS) {
                ssq0 += v0.x * v0.x + v0.y * v0.y;
                ssq1 += v1.x * v1.x + v1.y * v1.y;
                if (z == 0) {
                    const float2 w2 = *(const float2*)(wg + gc);
                    sdw0 += v0.x * w2.x + v0.y * w2.y;
                    sdw1 += v1.x * w2.x + v1.y * w2.y;
                }
            }
        }
        st_sq0[mt] = ssq0; st_sq1[mt] = ssq1;
        st_dw0[mt] = sdw0; st_dw1[mt] = sdw1;
    }

    if (STATS) {
        __syncthreads();
        float* s1 = (float*)sm;               // [128][4]
        float* s2 = (float*)sm + 128 * 4;
#pragma unroll
        for (int mt = 0; mt < 4; mt++) {
            float a0 = st_sq0[mt], a1 = st_sq1[mt];
            float b0 = st_dw0[mt], b1 = st_dw1[mt];
#pragma unroll
            for (int o = 1; o <= 2; o <<= 1) {
                a0 += __shfl_xor_sync(0xffffffffu, a0, o);
                a1 += __shfl_xor_sync(0xffffffffu, a1, o);
                b0 += __shfl_xor_sync(0xffffffffu, b0, o);
                b1 += __shfl_xor_sync(0xffffffffu, b1, o);
            }
            if ((lane & 3) == 0) {
                const int r0 = wm * 64 + mt * 16 + (lane >> 2);
                const int r1 = r0 + 8;
                s1[r0 * 4 + wn] = a0; s1[r1 * 4 + wn] = a1;
                if (z == 0) { s2[r0 * 4 + wn] = b0; s2[r1 * 4 + wn] = b1; }
            }
        }
        __syncthreads();
        if (tid < 128) {
            const size_t dst = (size_t)blockIdx.x * Mtot + rowA0 + tid;
            P1[dst] = s1[tid * 4] + s1[tid * 4 + 1] + s1[tid * 4 + 2] + s1[tid * 4 + 3];
            if (z == 0)
                P2[dst] = s2[tid * 4] + s2[tid * 4 + 1] + s2[tid * 4 + 2] + s2[tid * 4 + 3];
        }
    }
}

// ---------------------------------------------------------------------------
// Small kernels
// ---------------------------------------------------------------------------

#define N4_V   (M_VRT * 128)
#define N4_I   ((M_IMG / 4) * IMGDIM)
#define N4_WFC (DIM * IMGDIM / 4)
#define N4_W   (DIM * DIM / 4)
#define N4_TOTAL (N4_V + N4_I + N4_WFC + 4 * N4_W)

__global__ __launch_bounds__(256)
void cvt_all_kernel(const float4* __restrict__ v,  const float4* __restrict__ im,
                    const float4* __restrict__ wfc, const float4* __restrict__ wq,
                    const float4* __restrict__ wk,  const float4* __restrict__ wpr,
                    const float4* __restrict__ wfn)
{
    long i = (long)blockIdx.x * 256 + threadIdx.x;
    const float4* s; uint2* d;
    if (i < N4_V)                   { s = v;   d = (uint2*)g_vbf; }
    else if ((i -= N4_V)   < N4_I)  { s = im;  d = (uint2*)g_ibf; }
    else if ((i -= N4_I)   < N4_WFC){ s = wfc; d = (uint2*)g_wfc; }
    else if ((i -= N4_WFC) < N4_W)  { s = wq;  d = (uint2*)g_wq;  }
    else if ((i -= N4_W)   < N4_W)  { s = wk;  d = (uint2*)g_wk;  }
    else if ((i -= N4_W)   < N4_W)  { s = wpr; d = (uint2*)g_wpr; }
    else if ((i -= N4_W)   < N4_W)  { s = wfn; d = (uint2*)g_wfn; }
    else return;
    const float4 x = s[i];
    d[i] = make_uint2(pack_bf2(x.x, x.y), pack_bf2(x.z, x.w));
}

__global__ __launch_bounds__(256)
void rowstat_lite_kernel() {
    const int r = blockIdx.x * 256 + threadIdx.x;
    if (r >= M_ALL) return;
    float ssq = 0.f, sdw = 0.f, ssk = 0.f;
#pragma unroll
    for (int p = 0; p < NCT; p++) {
        ssq += g_pq1[p * M_ALL + r];
        sdw += g_pq2[p * M_ALL + r];
        ssk += g_pk1[p * M_ALL + r];
    }
    const float qs = 1.0f / fmaxf(sqrtf(ssq), 1e-12f);
    g_qs[r] = qs;
    g_ks[r] = 1.0f / fmaxf(sqrtf(ssk), 1e-12f);
    g_a[r]  = sdw * qs * ATT_SCALE;
}

__global__ __launch_bounds__(256)
void softmax_kernel() {
    const int b = blockIdx.x;
    const int tid = threadIdx.x;
    __shared__ float sh[NTOK];
    __shared__ float red[8];
    __shared__ float stat[2];
    float m = -1e30f;
    for (int i = tid; i < NTOK; i += 256) {
        const float v = g_a[b * NTOK + i]; sh[i] = v; m = fmaxf(m, v);
    }
#pragma unroll
    for (int o = 16; o > 0; o >>= 1) m = fmaxf(m, __shfl_down_sync(0xffffffffu, m, o));
    if ((tid & 31) == 0) red[tid >> 5] = m;
    __syncthreads();
    if (tid == 0) {
        float mm = red[0];
        for (int i = 1; i < 8; i++) mm = fmaxf(mm, red[i]);
        stat[0] = mm;
    }
    __syncthreads();
    const float M = stat[0];
    float s = 0.f;
    for (int i = tid; i < NTOK; i += 256) {
        const float e = expf(sh[i] - M); sh[i] = e; s += e;
    }
#pragma unroll
    for (int o = 16; o > 0; o >>= 1) s += __shfl_down_sync(0xffffffffu, s, o);
    __syncthreads();
    if ((tid & 31) == 0) red[tid >> 5] = s;
    __syncthreads();
    if (tid == 0) {
        float t = 0.f;
        for (int i = 0; i < 8; i++) t += red[i];
        stat[1] = 1.0f / t;
    }
    __syncthreads();
    const float inv = stat[1];
    for (int i = tid; i < NTOK; i += 256) g_a[b * NTOK + i] = sh[i] * inv;
}

__global__ __launch_bounds__(256)
void gsum_kernel() {
    const int b = blockIdx.x;
    const int d = threadIdx.x * 2;
    float ax = 0.f, ay = 0.f;
    for (int n = blockIdx.y; n < NTOK; n += NSPLIT) {
        const int row = b * NTOK + n;
        const float w = g_a[row] * g_qs[row];
        const float2 qv = *(const float2*)(g_q + (size_t)row * DIM + d);
        ax += w * qv.x; ay += w * qv.y;
    }
    g_gp[(size_t)blockIdx.y * BATCH * DIM + b * DIM + d]     = ax;
    g_gp[(size_t)blockIdx.y * BATCH * DIM + b * DIM + d + 1] = ay;
}

__global__ __launch_bounds__(256)
void greduce_kernel() {
    const int i = blockIdx.x * 256 + threadIdx.x;
    float s = 0.f;
#pragma unroll
    for (int p = 0; p < NSPLIT; p++) s += g_gp[(size_t)p * BATCH * DIM + i];
    g_g[i] = s;
}

__global__ __launch_bounds__(256)
void ymul_kernel() {
    const int idx = blockIdx.x * 256 + threadIdx.x;   // < M_VRT*128
    const int m = idx >> 7, j = idx & 127;
    const int b = m / NVERT, t = m - b * NVERT;
    const int row = b * NTOK + t;
    const float ks = g_ks[row];
    const float4 kv = ((const float4*)g_k)[(size_t)row * 128 + j];
    const float4 gv = ((const float4*)g_g)[b * 128 + j];
    ((uint2*)g_ybf)[idx] = make_uint2(
        pack_bf2(kv.x * gv.x * ks, kv.y * gv.y * ks),
        pack_bf2(kv.z * gv.z * ks, kv.w * gv.w * ks));
}

// ---------------------------------------------------------------------------

extern "C" void kernel_launch(void* const* d_in, const int* in_sizes, int n_in,
                              void* d_out, int out_size) {
    const float* verts   = (const float*)d_in[0];
    const float* img_f   = (const float*)d_in[1];
    const float* fc_w    = (const float*)d_in[2];
    const float* fc_b    = (const float*)d_in[3];
    const float* q_w     = (const float*)d_in[4];
    const float* q_b     = (const float*)d_in[5];
    const float* k_w     = (const float*)d_in[6];
    const float* k_b     = (const float*)d_in[7];
    const float* w_g     = (const float*)d_in[8];
    const float* proj_w  = (const float*)d_in[9];
    const float* proj_b  = (const float*)d_in[10];
    const float* final_w = (const float*)d_in[11];
    const float* final_b = (const float*)d_in[12];
    float* out = (float*)d_out;

    float *pq, *pk, *pqs, *ppq1, *ppq2, *ppk1;
    bf16 *pvbf, *pxibf, *pybf, *po1bf, *pwfc, *pwq, *pwk, *pwpr, *pwfn, *pibf;
    cudaGetSymbolAddress((void**)&pq,    g_q);
    cudaGetSymbolAddress((void**)&pk,    g_k);
    cudaGetSymbolAddress((void**)&pqs,   g_qs);
    cudaGetSymbolAddress((void**)&ppq1,  g_pq1);
    cudaGetSymbolAddress((void**)&ppq2,  g_pq2);
    cudaGetSymbolAddress((void**)&ppk1,  g_pk1);
    cudaGetSymbolAddress((void**)&pvbf,  g_vbf);
    cudaGetSymbolAddress((void**)&pibf,  g_ibf);
    cudaGetSymbolAddress((void**)&pxibf, g_xibf);
    cudaGetSymbolAddress((void**)&pybf,  g_ybf);
    cudaGetSymbolAddress((void**)&po1bf, g_o1bf);
    cudaGetSymbolAddress((void**)&pwfc,  g_wfc);
    cudaGetSymbolAddress((void**)&pwq,   g_wq);
    cudaGetSymbolAddress((void**)&pwk,   g_wk);
    cudaGetSymbolAddress((void**)&pwpr,  g_wpr);
    cudaGetSymbolAddress((void**)&pwfn,  g_wfn);

    cudaFuncSetAttribute(gemm_bf<2048,0,1>, cudaFuncAttributeMaxDynamicSharedMemorySize, GEMM_SMEM);
    cudaFuncSetAttribute(gemm_bf<512,1,0>,  cudaFuncAttributeMaxDynamicSharedMemorySize, GEMM_SMEM);
    cudaFuncSetAttribute(gemm_bf<512,0,1>,  cudaFuncAttributeMaxDynamicSharedMemorySize, GEMM_SMEM);
    cudaFuncSetAttribute(gemm_bf<512,0,0>,  cudaFuncAttributeMaxDynamicSharedMemorySize, GEMM_SMEM);

    const RMap direct    = {1 << 30, 0, 0};
    const RMap vert_emap = {NVERT, NTOK, 0};

    // C0: single fused fp32 -> bf16 convert
    cvt_all_kernel<<<N4_TOTAL / 256, 256>>>(
        (const float4*)verts, (const float4*)img_f, (const float4*)fc_w,
        (const float4*)q_w, (const float4*)k_w, (const float4*)proj_w,
        (const float4*)final_w);

    // G1: img projection -> xi (bf16 out), K=2048
    gemm_bf<2048,0,1><<<dim3(DIM / BN, M_IMG / BM), 256, GEMM_SMEM>>>(
        pibf, nullptr, pwfc, nullptr, fc_b, nullptr,
        nullptr, nullptr, nullptr,
        pxibf, nullptr, nullptr, nullptr, nullptr, 0, direct, direct);

    // G23: fused q/k GEMMs (grid.z selects weight/bias/output/stat buffers)
    gemm_bf<512,1,0><<<dim3(DIM / BN, M_ALL / BM, 2), 256, GEMM_SMEM>>>(
        pvbf, pxibf, pwq, pwk, q_b, k_b,
        nullptr, nullptr, w_g,
        pq, pk, ppq1, ppk1, ppq2, M_ALL, direct, direct);

    rowstat_lite_kernel<<<(M_ALL + 255) / 256, 256>>>();
    softmax_kernel<<<BATCH, 256>>>();
    gsum_kernel<<<dim3(BATCH, NSPLIT), 256>>>();
    greduce_kernel<<<(BATCH * DIM) / 256, 256>>>();
    ymul_kernel<<<(M_VRT * 128) / 256, 256>>>();

    // G4: proj + qs*q residual -> o1 (bf16 out)
    gemm_bf<512,0,1><<<dim3(DIM / BN, M_VRT / BM), 256, GEMM_SMEM>>>(
        pybf, nullptr, pwpr, nullptr, proj_b, nullptr,
        pq, pqs, nullptr,
        po1bf, nullptr, nullptr, nullptr, nullptr, 0, direct, vert_emap);

    // G5: final + verts residual -> out fp32
    gemm_bf<512,0,0><<<dim3(DIM / BN, M_VRT / BM), 256, GEMM_SMEM>>>(
        po1bf, nullptr, pwfn, nullptr, final_b, nullptr,
        verts, nullptr, nullptr,
        out, nullptr, nullptr, nullptr, nullptr, 0, direct, direct);
}